// round 5
// baseline (speedup 1.0000x reference)
#include <cuda_runtime.h>
#include <cuda_bf16.h>
#include <cstdint>

#define QN    2048
#define EN    256
#define TOTC  40
#define NB    8
#define LMAXC 5
#define NH    8
#define NTAB  2048

typedef __nv_bfloat16 bf16;

// ---------------- scratch ----------------
__device__ float g_trans [TOTC*QN*3];
__device__ float g_kp    [TOTC*QN*EN];
__device__ float g_vp    [TOTC*QN*EN];
__device__ float g_ego   [2][NB*QN*EN];
__device__ float g_qp    [NB*QN*EN];
__device__ float g_table [3*NTAB*EN];
__device__ float g_bkp   [EN];
__device__ float g_freq  [EN];
__device__ int   g_cav_batch[TOTC];
__device__ int   g_cav_local[TOTC];
__device__ int   g_batch_n  [NB];
__device__ int   g_batch_off[NB];

// bf16 hi/lo operand buffers
__device__ bf16 g_xhi[TOTC*QN*EN], g_xlo[TOTC*QN*EN];
__device__ bf16 g_hhi[TOTC*QN*EN], g_hlo[TOTC*QN*EN];
__device__ bf16 g_ehi[2][NB*QN*EN], g_elo[2][NB*QN*EN];
__device__ bf16 g_chi[NB*QN*EN],   g_clo[NB*QN*EN];
__device__ bf16 g_wcat_hi[EN*512], g_wcat_lo[EN*512];
__device__ bf16 g_wq_hi[EN*EN], g_wq_lo[EN*EN];
__device__ bf16 g_wv_hi[EN*EN], g_wv_lo[EN*EN];
__device__ bf16 g_wo_hi[EN*EN], g_wo_lo[EN*EN];

__device__ __forceinline__ void split1(float v, bf16& h, bf16& l) {
    h = __float2bfloat16_rn(v);
    l = __float2bfloat16_rn(v - __bfloat162float(h));
}

// ---------------- setup ----------------
__global__ void setup_kernel(const long long* __restrict__ rl64) {
    int t = threadIdx.x;
    if (t == 0) {
        bool ok64 = true;
        for (int b = 0; b < NB; b++) {
            long long v = rl64[b];
            if (v < 1 || v > LMAXC) ok64 = false;
        }
        const int* rl32 = (const int*)rl64;
        int acc = 0;
        for (int c = 0; c < TOTC; c++) { g_cav_batch[c] = 0; g_cav_local[c] = 0; }
        for (int b = 0; b < NB; b++) {
            int n = ok64 ? (int)rl64[b] : rl32[b];
            if (n < 1) n = 1;
            if (n > LMAXC) n = LMAXC;
            g_batch_n[b] = n; g_batch_off[b] = acc;
            for (int l = 0; l < n; l++) {
                int c = acc + l;
                if (c < TOTC) { g_cav_batch[c] = b; g_cav_local[c] = l; }
            }
            acc += n;
        }
    }
    for (int j = t; j < EN; j += blockDim.x) {
        float ex = (2.0f * (float)(j >> 1)) / (float)EN;
        g_freq[j] = 6.283185307179586f * expf(-ex * 9.210340371976184f);
    }
}

// ---------------- trans ----------------
__global__ void trans_kernel(const float* __restrict__ rp, const float* __restrict__ ptm) {
    int idx = blockIdx.x * blockDim.x + threadIdx.x;
    if (idx >= TOTC * QN) return;
    int c = idx / QN;
    int b = g_cav_batch[c], l = g_cav_local[c];
    float r0 = rp[idx*3+0] * 281.6f - 140.8f;
    float r1 = rp[idx*3+1] *  80.0f -  40.0f;
    float r2 = rp[idx*3+2] *   4.0f -   3.0f;
    const float* T = ptm + (size_t)((b * LMAXC + l) * LMAXC) * 16;
    #pragma unroll
    for (int i = 0; i < 3; i++) {
        float z = fmaf(T[i*4+0], r0, fmaf(T[i*4+1], r1, fmaf(T[i*4+2], r2, T[i*4+3])));
        g_trans[idx*3+i] = 1.0f / (1.0f + expf(-z));
    }
}

// ---------------- ego init (fp32 + hi/lo) ----------------
__global__ void ego_init_kernel(const float* __restrict__ x) {
    int idx = blockIdx.x * blockDim.x + threadIdx.x;
    if (idx >= NB * QN * (EN/4)) return;
    int e4 = idx & 63;
    int rq = idx >> 6;
    int b  = rq >> 11;
    int q  = rq & (QN-1);
    int off = g_batch_off[b];
    float4 v = *(const float4*)(x + (size_t)q*(TOTC*EN) + off*EN + e4*4);
    size_t o = (size_t)rq*EN + e4*4;
    *(float4*)(&g_ego[0][o]) = v;
    bf16 h[4], l[4];
    split1(v.x, h[0], l[0]); split1(v.y, h[1], l[1]);
    split1(v.z, h[2], l[2]); split1(v.w, h[3], l[3]);
    *(uint2*)&g_ehi[0][o] = *(uint2*)h;
    *(uint2*)&g_elo[0][o] = *(uint2*)l;
}

// ---------------- x split ----------------
__global__ void xsplit_kernel(const float* __restrict__ x) {
    int idx = blockIdx.x * blockDim.x + threadIdx.x;
    if (idx >= TOTC*QN*EN/4) return;
    float4 v = *(const float4*)(x + (size_t)idx*4);
    bf16 h[4], l[4];
    split1(v.x, h[0], l[0]); split1(v.y, h[1], l[1]);
    split1(v.z, h[2], l[2]); split1(v.w, h[3], l[3]);
    *(uint2*)&g_xhi[(size_t)idx*4] = *(uint2*)h;
    *(uint2*)&g_xlo[(size_t)idx*4] = *(uint2*)l;
}

// ---------------- weight split: Wq, Wv, Wo ----------------
__global__ void wsplit_kernel(const float* __restrict__ in_w, const float* __restrict__ ow) {
    int i = blockIdx.x * blockDim.x + threadIdx.x;
    if (i >= EN*EN) return;
    bf16 h, l;
    split1(in_w[i],            h, l); g_wq_hi[i] = h; g_wq_lo[i] = l;
    split1(in_w[2*EN*EN + i],  h, l); g_wv_hi[i] = h; g_wv_lo[i] = l;
    split1(ow[i],              h, l); g_wo_hi[i] = h; g_wo_lo[i] = l;
}

// ---------------- wcat = [Wk | Wk@W2] (bf16 hi/lo), bkp = bk + Wk@b2 ----------------
__global__ void wkk_kernel(const float* __restrict__ in_w, const float* __restrict__ in_b,
                           const float* __restrict__ w2,   const float* __restrict__ b2) {
    __shared__ float sWk[EN];
    __shared__ float red[EN];
    int n = blockIdx.x, j = threadIdx.x;
    sWk[j] = in_w[(size_t)(EN + n)*EN + j];
    __syncthreads();
    float a0 = 0.f, a1 = 0.f, a2 = 0.f, a3 = 0.f;
    #pragma unroll 4
    for (int m = 0; m < EN; m += 4) {
        a0 = fmaf(sWk[m+0], w2[(size_t)(m+0)*EN + j], a0);
        a1 = fmaf(sWk[m+1], w2[(size_t)(m+1)*EN + j], a1);
        a2 = fmaf(sWk[m+2], w2[(size_t)(m+2)*EN + j], a2);
        a3 = fmaf(sWk[m+3], w2[(size_t)(m+3)*EN + j], a3);
    }
    float acc = (a0 + a1) + (a2 + a3);
    bf16 h, l;
    split1(sWk[j], h, l);
    g_wcat_hi[(size_t)n*512 + j] = h;  g_wcat_lo[(size_t)n*512 + j] = l;
    split1(acc, h, l);
    g_wcat_hi[(size_t)n*512 + EN + j] = h;  g_wcat_lo[(size_t)n*512 + EN + j] = l;
    // parallel bkp reduction
    red[j] = sWk[j] * b2[j];
    __syncthreads();
    for (int s = 128; s > 0; s >>= 1) {
        if (j < s) red[j] += red[j + s];
        __syncthreads();
    }
    if (j == 0) g_bkp[n] = in_b[EN + n] + red[0];
}

// ---------------- table GEMM (fp32 SIMT, small) ----------------
__global__ __launch_bounds__(256) void table_kernel(const float* __restrict__ W1) {
    const int bm = blockIdx.x, bn = blockIdx.y;
    const int d  = bm / (NTAB/128);
    const int ib = (bm % (NTAB/128)) * 128;
    __shared__ float As[16][132];
    __shared__ float Bs[16][132];
    __shared__ float fr[EN];
    const int t  = threadIdx.x;
    const int tm = t >> 4, tn = t & 15;
    const int lr = t >> 2, lc4 = t & 3;
    const int n0 = bn * 128;
    fr[t] = g_freq[t & (EN-1)];
    __syncthreads();
    float acc[8][8] = {};
    const float inv = 1.0f / (float)(NTAB - 1);
    for (int kt = 0; kt < 16; kt++) {
        const int k0 = kt * 16;
        #pragma unroll
        for (int rr = 0; rr < 2; rr++) {
            const int m = lr + rr * 64;
            const float tv = (float)(ib + m) * inv;
            #pragma unroll
            for (int i = 0; i < 4; i++) {
                const int kk = lc4*4 + i, j = k0 + kk;
                const float arg = tv * fr[j];
                As[kk][m] = (j & 1) ? __cosf(arg) : __sinf(arg);
            }
        }
        #pragma unroll
        for (int rr = 0; rr < 2; rr++) {
            const int nn = lr + rr * 64;
            const float4 v = *(const float4*)(W1 + (size_t)(n0+nn)*768 + d*256 + k0 + lc4*4);
            Bs[lc4*4+0][nn] = v.x; Bs[lc4*4+1][nn] = v.y;
            Bs[lc4*4+2][nn] = v.z; Bs[lc4*4+3][nn] = v.w;
        }
        __syncthreads();
        #pragma unroll
        for (int kk = 0; kk < 16; kk++) {
            float af[8], bf[8];
            *(float4*)&af[0] = *(const float4*)&As[kk][tm*8];
            *(float4*)&af[4] = *(const float4*)&As[kk][tm*8+4];
            *(float4*)&bf[0] = *(const float4*)&Bs[kk][tn*8];
            *(float4*)&bf[4] = *(const float4*)&Bs[kk][tn*8+4];
            #pragma unroll
            for (int i = 0; i < 8; i++)
                #pragma unroll
                for (int j = 0; j < 8; j++)
                    acc[i][j] = fmaf(af[i], bf[j], acc[i][j]);
        }
        __syncthreads();
    }
    #pragma unroll
    for (int i = 0; i < 8; i++) {
        const int row = ib + tm*8 + i;
        float* dst = g_table + ((size_t)(d*NTAB + row))*EN + n0 + tn*8;
        *(float4*)(dst)   = make_float4(acc[i][0], acc[i][1], acc[i][2], acc[i][3]);
        *(float4*)(dst+4) = make_float4(acc[i][4], acc[i][5], acc[i][6], acc[i][7]);
    }
}

// ---------------- hidden = relu(b1 + sum_d lerp(table_d, t_d)) -> hi/lo bf16 ----------------
__global__ void bev_lookup(const float* __restrict__ b1) {
    int idx = blockIdx.x * blockDim.x + threadIdx.x;
    if (idx >= TOTC*QN*(EN/4)) return;
    int n4  = idx & 63;
    int row = idx >> 6;
    int cav = row >> 11;
    if (g_cav_local[cav] == 0 || g_batch_n[g_cav_batch[cav]] <= 1) return;
    float4 acc = *(const float4*)(b1 + n4*4);
    #pragma unroll
    for (int d = 0; d < 3; d++) {
        float tv = g_trans[(size_t)row*3 + d];
        float u  = tv * (float)(NTAB - 1);
        int i0 = (int)u;
        if (i0 < 0) i0 = 0;
        if (i0 > NTAB-2) i0 = NTAB-2;
        float w = u - (float)i0;
        const float* r = g_table + ((size_t)(d*NTAB + i0))*EN + n4*4;
        float4 a = *(const float4*)r;
        float4 b = *(const float4*)(r + EN);
        acc.x = fmaf(w, b.x - a.x, acc.x + a.x);
        acc.y = fmaf(w, b.y - a.y, acc.y + a.y);
        acc.z = fmaf(w, b.z - a.z, acc.z + a.z);
        acc.w = fmaf(w, b.w - a.w, acc.w + a.w);
    }
    float o0 = fmaxf(acc.x,0.f), o1 = fmaxf(acc.y,0.f), o2 = fmaxf(acc.z,0.f), o3 = fmaxf(acc.w,0.f);
    bf16 h[4], l[4];
    split1(o0, h[0], l[0]); split1(o1, h[1], l[1]);
    split1(o2, h[2], l[2]); split1(o3, h[3], l[3]);
    size_t o = (size_t)row*EN + n4*4;
    *(uint2*)&g_hhi[o] = *(uint2*)h;
    *(uint2*)&g_hlo[o] = *(uint2*)l;
}

// ================= async bf16-split tensor GEMM =================
__device__ __forceinline__ uint32_t s2u(const void* p) {
    uint32_t a;
    asm("{ .reg .u64 t; cvta.to.shared.u64 t, %1; cvt.u32.u64 %0, t; }" : "=r"(a) : "l"(p));
    return a;
}
__device__ __forceinline__ void ldm4(uint32_t* f, uint32_t addr) {
    asm volatile("ldmatrix.sync.aligned.m8n8.x4.shared.b16 {%0,%1,%2,%3}, [%4];"
        : "=r"(f[0]),"=r"(f[1]),"=r"(f[2]),"=r"(f[3]) : "r"(addr));
}
__device__ __forceinline__ void mmabf(float* c, const uint32_t* a, const uint32_t* b) {
    asm volatile("mma.sync.aligned.m16n8k16.row.col.f32.bf16.bf16.f32 "
        "{%0,%1,%2,%3}, {%4,%5,%6,%7}, {%8,%9}, {%0,%1,%2,%3};"
        : "+f"(c[0]),"+f"(c[1]),"+f"(c[2]),"+f"(c[3])
        : "r"(a[0]),"r"(a[1]),"r"(a[2]),"r"(a[3]), "r"(b[0]),"r"(b[1]));
}
__device__ __forceinline__ void cpa16(uint32_t dst, const void* src) {
    asm volatile("cp.async.cg.shared.global [%0], [%1], 16;" :: "r"(dst), "l"(src));
}
#define CP_COMMIT()  asm volatile("cp.async.commit_group;")
#define CP_WAIT1()   asm volatile("cp.async.wait_group 1;")

#define TSTR 24
#define TSZ  (128*TSTR)
#define DG_SMEM (3*4*TSZ*2)     // 73728 B

// MODE 1: kp = [x|hidden] @ wcat^T + bkp   (K=512)
// MODE 2: vp = x @ Wv^T + bv
// MODE 3: qp = ego[sel] @ Wq^T + bq
// MODE 4: ego[sel^1] = (n-1)*(ego[sel] + ctx @ Wo^T + bo)   (+ hi/lo write)
template<int MODE, int KT>
__global__ __launch_bounds__(256) void mma_gemm(const float* __restrict__ bias, int sel) {
    extern __shared__ __align__(16) char smraw[];
    const int bm = blockIdx.x, bn = blockIdx.y;
    int cav = 0; float scale = 1.0f;
    if (MODE == 1 || MODE == 2) {
        cav = bm >> 4;
        if (g_cav_local[cav] == 0 || g_batch_n[g_cav_batch[cav]] <= 1) return;
    } else {
        int batch = bm >> 4;
        int n = g_batch_n[batch];
        if (n <= 1) return;
        scale = (float)(n - 1);
    }
    const int t    = threadIdx.x;
    const int lane = t & 31, wid = t >> 5;
    const int wm   = wid & 3, wn = wid >> 2;
    const int m0   = bm * 128, n0 = bn * 128;
    const int lrow = t >> 1;
    const int lk   = (t & 1) * 8;
    const int eo   = lrow * TSTR + lk;

    const int aoff = (wm*32 + (lane & 7) + ((lane >> 3) & 1) * 8) * TSTR + (lane >> 4) * 8;
    const int boff = (wn*64 + (lane & 7) + (lane >> 4) * 8) * TSTR + ((lane >> 3) & 1) * 8;
    const uint32_t smb = s2u(smraw);

    auto issue = [&](int kt) {
        const int stage = kt % 3;
        const int k0 = kt * 16 + lk;
        const int arow = m0 + lrow;
        const bf16 *sa_hi, *sa_lo;
        if (MODE == 1) {
            if (k0 < 256) { int q = arow & (QN-1); size_t o = (size_t)q*(TOTC*EN) + cav*EN + k0;
                            sa_hi = g_xhi + o; sa_lo = g_xlo + o; }
            else          { size_t o = (size_t)arow*EN + (k0 - 256);
                            sa_hi = g_hhi + o; sa_lo = g_hlo + o; }
        } else if (MODE == 2) {
            int q = arow & (QN-1); size_t o = (size_t)q*(TOTC*EN) + cav*EN + k0;
            sa_hi = g_xhi + o; sa_lo = g_xlo + o;
        } else if (MODE == 3) {
            size_t o = (size_t)arow*EN + k0;
            sa_hi = g_ehi[sel & 1] + o; sa_lo = g_elo[sel & 1] + o;
        } else {
            size_t o = (size_t)arow*EN + k0;
            sa_hi = g_chi + o; sa_lo = g_clo + o;
        }
        const bf16 *sw_hi, *sw_lo;
        if (MODE == 1) { size_t o = (size_t)(n0 + lrow)*512 + k0; sw_hi = g_wcat_hi + o; sw_lo = g_wcat_lo + o; }
        else {
            size_t o = (size_t)(n0 + lrow)*EN + k0;
            if (MODE == 2)      { sw_hi = g_wv_hi + o; sw_lo = g_wv_lo + o; }
            else if (MODE == 3) { sw_hi = g_wq_hi + o; sw_lo = g_wq_lo + o; }
            else                { sw_hi = g_wo_hi + o; sw_lo = g_wo_lo + o; }
        }
        uint32_t base = smb + (uint32_t)(stage*4*TSZ + eo)*2;
        cpa16(base + 0*TSZ*2, sa_hi);
        cpa16(base + 1*TSZ*2, sa_lo);
        cpa16(base + 2*TSZ*2, sw_hi);
        cpa16(base + 3*TSZ*2, sw_lo);
    };

    float acc[2][8][4] = {};

    issue(0); CP_COMMIT();
    issue(1); CP_COMMIT();

    for (int kt = 0; kt < KT; kt++) {
        CP_WAIT1();
        __syncthreads();
        const int stage = kt % 3;
        const uint32_t bA  = smb + (uint32_t)((stage*4+0)*TSZ + aoff)*2;
        const uint32_t bAl = smb + (uint32_t)((stage*4+1)*TSZ + aoff)*2;
        const uint32_t bW  = smb + (uint32_t)((stage*4+2)*TSZ + boff)*2;
        const uint32_t bWl = smb + (uint32_t)((stage*4+3)*TSZ + boff)*2;

        uint32_t Ahi[2][4], Alo[2][4];
        #pragma unroll
        for (int ms = 0; ms < 2; ms++) {
            ldm4(Ahi[ms], bA  + ms*16*TSTR*2);
            ldm4(Alo[ms], bAl + ms*16*TSTR*2);
        }
        #pragma unroll
        for (int np = 0; np < 4; np++) {
            uint32_t Bhi[4], Blo[4];
            ldm4(Bhi, bW  + np*16*TSTR*2);
            ldm4(Blo, bWl + np*16*TSTR*2);
            #pragma unroll
            for (int ms = 0; ms < 2; ms++) {
                mmabf(acc[ms][2*np],   Ahi[ms], Bhi);
                mmabf(acc[ms][2*np+1], Ahi[ms], Bhi+2);
                mmabf(acc[ms][2*np],   Alo[ms], Bhi);
                mmabf(acc[ms][2*np+1], Alo[ms], Bhi+2);
                mmabf(acc[ms][2*np],   Ahi[ms], Blo);
                mmabf(acc[ms][2*np+1], Ahi[ms], Blo+2);
            }
        }
        if (kt + 2 < KT) issue(kt + 2);
        CP_COMMIT();
    }

    // epilogue
    const float* bptr = (MODE == 1) ? g_bkp : bias;
    #pragma unroll
    for (int ms = 0; ms < 2; ms++) {
        const int row = m0 + wm*32 + ms*16 + (lane >> 2);
        #pragma unroll
        for (int ns = 0; ns < 8; ns++) {
            const int col = n0 + wn*64 + ns*8 + (lane & 3)*2;
            const float2 bv = *(const float2*)(bptr + col);
            #pragma unroll
            for (int h = 0; h < 2; h++) {
                const int r = row + h*8;
                float v0 = acc[ms][ns][2*h]   + bv.x;
                float v1 = acc[ms][ns][2*h+1] + bv.y;
                const size_t o = (size_t)r*EN + col;
                if (MODE == 1)      *(float2*)(g_kp + o) = make_float2(v0, v1);
                else if (MODE == 2) *(float2*)(g_vp + o) = make_float2(v0, v1);
                else if (MODE == 3) *(float2*)(g_qp + o) = make_float2(v0, v1);
                else {
                    const float2 er = *(const float2*)(g_ego[sel & 1] + o);
                    v0 = scale * (er.x + v0);
                    v1 = scale * (er.y + v1);
                    *(float2*)(g_ego[(sel ^ 1) & 1] + o) = make_float2(v0, v1);
                    bf16 h0, l0, h1, l1;
                    split1(v0, h0, l0); split1(v1, h1, l1);
                    bf16 hp[2] = {h0, h1}, lp[2] = {l0, l1};
                    *(uint32_t*)&g_ehi[(sel ^ 1) & 1][o] = *(uint32_t*)hp;
                    *(uint32_t*)&g_elo[(sel ^ 1) & 1][o] = *(uint32_t*)lp;
                }
            }
        }
    }
}

// ---------------- degenerate attention (writes ctx hi/lo) ----------------
__global__ void attn_kernel() {
    int w = (blockIdx.x * blockDim.x + threadIdx.x) >> 5;
    int lane = threadIdx.x & 31;
    if (w >= NB * QN * NH) return;
    int h  = w & 7;
    int bq = w >> 3;
    int b  = bq >> 11;
    int q  = bq & (QN - 1);
    int n  = g_batch_n[b];
    if (n <= 1) return;
    int nm  = n - 1;
    int off = g_batch_off[b];
    int col = h * 32 + lane;

    float qv = g_qp[(size_t)bq*EN + col];
    float sc[LMAXC - 1];
    for (int m = 0; m < nm; m++) {
        int c = off + 1 + m;
        float p = qv * g_kp[(size_t)(c*QN + q)*EN + col];
        #pragma unroll
        for (int o = 16; o; o >>= 1) p += __shfl_xor_sync(0xffffffffu, p, o);
        sc[m] = p * 0.17677669529663687f;
    }
    float mx = -1e30f;
    for (int m = 0; m < nm; m++) mx = fmaxf(mx, sc[m]);
    float s = 0.0f, wt[LMAXC - 1];
    for (int m = 0; m < nm; m++) { wt[m] = __expf(sc[m] - mx); s += wt[m]; }
    float inv = 1.0f / s;
    float ctx = 0.0f;
    for (int m = 0; m < nm; m++) {
        int c = off + 1 + m;
        ctx = fmaf(wt[m] * inv, g_vp[(size_t)(c*QN + q)*EN + col], ctx);
    }
    bf16 hh, ll;
    split1(ctx, hh, ll);
    g_chi[(size_t)bq*EN + col] = hh;
    g_clo[(size_t)bq*EN + col] = ll;
}

// ---------------- final merge ----------------
__global__ void out_kernel(const float* __restrict__ x, float* __restrict__ out, int fin) {
    int idx = blockIdx.x * blockDim.x + threadIdx.x;
    if (idx >= QN * TOTC * (EN/4)) return;
    int e4 = idx & 63;
    int qc = idx >> 6;
    int c  = qc % TOTC;
    int q  = qc / TOTC;
    int b  = g_cav_batch[c], l = g_cav_local[c];
    float4 v;
    if (l == 0 && g_batch_n[b] > 1)
        v = *(const float4*)(g_ego[fin & 1] + (size_t)(b*QN + q)*EN + e4*4);
    else
        v = *(const float4*)(x + (size_t)idx*4);
    *(float4*)(out + (size_t)idx*4) = v;
}

// ---------------- launch ----------------
extern "C" void kernel_launch(void* const* d_in, const int* in_sizes, int n_in,
                              void* d_out, int out_size) {
    const float*     x    = (const float*)d_in[0];
    const float*     rp   = (const float*)d_in[1];
    const float*     ptm  = (const float*)d_in[2];
    const long long* rl   = (const long long*)d_in[3];
    const float*     in_w = (const float*)d_in[4];
    const float*     in_b = (const float*)d_in[5];
    const float*     ow   = (const float*)d_in[6];
    const float*     ob   = (const float*)d_in[7];
    const float*     w1   = (const float*)d_in[8];
    const float*     b1   = (const float*)d_in[9];
    const float*     w2   = (const float*)d_in[10];
    const float*     b2   = (const float*)d_in[11];
    float* out = (float*)d_out;

    static bool attr_done = false;
    if (!attr_done) {
        cudaFuncSetAttribute(mma_gemm<1,32>, cudaFuncAttributeMaxDynamicSharedMemorySize, DG_SMEM);
        cudaFuncSetAttribute(mma_gemm<2,16>, cudaFuncAttributeMaxDynamicSharedMemorySize, DG_SMEM);
        cudaFuncSetAttribute(mma_gemm<3,16>, cudaFuncAttributeMaxDynamicSharedMemorySize, DG_SMEM);
        cudaFuncSetAttribute(mma_gemm<4,16>, cudaFuncAttributeMaxDynamicSharedMemorySize, DG_SMEM);
        attr_done = true;
    }

    setup_kernel<<<1, 256>>>(rl);
    trans_kernel<<<(TOTC*QN + 255)/256, 256>>>(rp, ptm);
    ego_init_kernel<<<(NB*QN*(EN/4) + 255)/256, 256>>>(x);
    xsplit_kernel<<<(TOTC*QN*EN/4 + 255)/256, 256>>>(x);
    wsplit_kernel<<<(EN*EN + 255)/256, 256>>>(in_w, ow);
    wkk_kernel<<<EN, EN>>>(in_w, in_b, w2, b2);
    table_kernel<<<dim3(3*NTAB/128, 2), 256>>>(w1);
    bev_lookup<<<(TOTC*QN*(EN/4) + 255)/256, 256>>>(b1);

    dim3 gcav(TOTC*QN/128, 2);
    mma_gemm<1,32><<<gcav, 256, DG_SMEM>>>(nullptr,     0);    // kp (K=512)
    mma_gemm<2,16><<<gcav, 256, DG_SMEM>>>(in_b + 512,  0);    // vp

    dim3 gego(NB*QN/128, 2);
    int cur = 0;
    for (int it = 0; it < 2; it++) {
        mma_gemm<3,16><<<gego, 256, DG_SMEM>>>(in_b, cur);     // qp
        attn_kernel<<<NB*QN*NH*32/256, 256>>>();               // ctx
        mma_gemm<4,16><<<gego, 256, DG_SMEM>>>(ob,   cur);     // ego
        cur ^= 1;
    }
    out_kernel<<<(QN*TOTC*(EN/4) + 255)/256, 256>>>(x, out, cur);
}

// round 7
// speedup vs baseline: 1.1423x; 1.1423x over previous
#include <cuda_runtime.h>
#include <cuda_bf16.h>
#include <cstdint>

#define QN    2048
#define EN    256
#define TOTC  40
#define NB    8
#define LMAXC 5
#define NH    8
#define NTAB  2048

// ---------------- scratch ----------------
__device__ float g_trans [TOTC*QN*3];
__device__ float g_hidden[TOTC*QN*EN];
__device__ float g_kp    [TOTC*QN*EN];
__device__ float g_vp    [TOTC*QN*EN];
__device__ float g_ego   [2][NB*QN*EN];
__device__ float g_qp    [NB*QN*EN];
__device__ float g_ctx   [NB*QN*EN];
__device__ float g_table [3*NTAB*EN];
__device__ float g_wcat  [EN*512];
__device__ float g_bkp   [EN];
__device__ float g_freq  [EN];
__device__ int   g_cav_batch[TOTC];
__device__ int   g_cav_local[TOTC];
__device__ int   g_batch_n  [NB];
__device__ int   g_batch_off[NB];

// ---------------- setup ----------------
__global__ void setup_kernel(const long long* __restrict__ rl64) {
    int t = threadIdx.x;
    if (t == 0) {
        bool ok64 = true;
        for (int b = 0; b < NB; b++) {
            long long v = rl64[b];
            if (v < 1 || v > LMAXC) ok64 = false;
        }
        const int* rl32 = (const int*)rl64;
        int acc = 0;
        for (int c = 0; c < TOTC; c++) { g_cav_batch[c] = 0; g_cav_local[c] = 0; }
        for (int b = 0; b < NB; b++) {
            int n = ok64 ? (int)rl64[b] : rl32[b];
            if (n < 1) n = 1;
            if (n > LMAXC) n = LMAXC;
            g_batch_n[b] = n; g_batch_off[b] = acc;
            for (int l = 0; l < n; l++) {
                int c = acc + l;
                if (c < TOTC) { g_cav_batch[c] = b; g_cav_local[c] = l; }
            }
            acc += n;
        }
    }
    for (int j = t; j < EN; j += blockDim.x) {
        float ex = (2.0f * (float)(j >> 1)) / (float)EN;
        g_freq[j] = 6.283185307179586f * expf(-ex * 9.210340371976184f);
    }
}

// ---------------- trans ----------------
__global__ void trans_kernel(const float* __restrict__ rp, const float* __restrict__ ptm) {
    int idx = blockIdx.x * blockDim.x + threadIdx.x;
    if (idx >= TOTC * QN) return;
    int c = idx / QN;
    int b = g_cav_batch[c], l = g_cav_local[c];
    float r0 = rp[idx*3+0] * 281.6f - 140.8f;
    float r1 = rp[idx*3+1] *  80.0f -  40.0f;
    float r2 = rp[idx*3+2] *   4.0f -   3.0f;
    const float* T = ptm + (size_t)((b * LMAXC + l) * LMAXC) * 16;
    #pragma unroll
    for (int i = 0; i < 3; i++) {
        float z = fmaf(T[i*4+0], r0, fmaf(T[i*4+1], r1, fmaf(T[i*4+2], r2, T[i*4+3])));
        g_trans[idx*3+i] = 1.0f / (1.0f + expf(-z));
    }
}

// ---------------- ego init ----------------
__global__ void ego_init_kernel(const float* __restrict__ x) {
    int idx = blockIdx.x * blockDim.x + threadIdx.x;
    if (idx >= NB * QN * (EN/4)) return;
    int e4 = idx & 63;
    int rq = idx >> 6;
    int b  = rq >> 11;
    int q  = rq & (QN-1);
    int off = g_batch_off[b];
    float4 v = *(const float4*)(x + (size_t)q*(TOTC*EN) + off*EN + e4*4);
    *(float4*)(&g_ego[0][(size_t)rq*EN + e4*4]) = v;
}

// ---------------- wcat = [Wk | Wk@W2], bkp = bk + Wk@b2 ----------------
__global__ void wkk_kernel(const float* __restrict__ in_w, const float* __restrict__ in_b,
                           const float* __restrict__ w2,   const float* __restrict__ b2) {
    __shared__ float sWk[EN];
    __shared__ float red[EN];
    int n = blockIdx.x, j = threadIdx.x;
    sWk[j] = in_w[(size_t)(EN + n)*EN + j];
    __syncthreads();
    float a0 = 0.f, a1 = 0.f, a2 = 0.f, a3 = 0.f;
    #pragma unroll 4
    for (int m = 0; m < EN; m += 4) {
        a0 = fmaf(sWk[m+0], w2[(size_t)(m+0)*EN + j], a0);
        a1 = fmaf(sWk[m+1], w2[(size_t)(m+1)*EN + j], a1);
        a2 = fmaf(sWk[m+2], w2[(size_t)(m+2)*EN + j], a2);
        a3 = fmaf(sWk[m+3], w2[(size_t)(m+3)*EN + j], a3);
    }
    float acc = (a0 + a1) + (a2 + a3);
    g_wcat[(size_t)n*512 + j]      = sWk[j];
    g_wcat[(size_t)n*512 + EN + j] = acc;
    red[j] = sWk[j] * b2[j];
    __syncthreads();
    for (int s = 128; s > 0; s >>= 1) {
        if (j < s) red[j] += red[j + s];
        __syncthreads();
    }
    if (j == 0) g_bkp[n] = in_b[EN + n] + red[0];
}

// ---------------- table GEMM (fp32 SIMT, small) ----------------
__global__ __launch_bounds__(256) void table_kernel(const float* __restrict__ W1) {
    const int bm = blockIdx.x, bn = blockIdx.y;
    const int d  = bm / (NTAB/128);
    const int ib = (bm % (NTAB/128)) * 128;
    __shared__ float As[16][132];
    __shared__ float Bs[16][132];
    __shared__ float fr[EN];
    const int t  = threadIdx.x;
    const int tm = t >> 4, tn = t & 15;
    const int lr = t >> 2, lc4 = t & 3;
    const int n0 = bn * 128;
    fr[t] = g_freq[t & (EN-1)];
    __syncthreads();
    float acc[8][8] = {};
    const float inv = 1.0f / (float)(NTAB - 1);
    for (int kt = 0; kt < 16; kt++) {
        const int k0 = kt * 16;
        #pragma unroll
        for (int rr = 0; rr < 2; rr++) {
            const int m = lr + rr * 64;
            const float tv = (float)(ib + m) * inv;
            #pragma unroll
            for (int i = 0; i < 4; i++) {
                const int kk = lc4*4 + i, j = k0 + kk;
                const float arg = tv * fr[j];
                As[kk][m] = (j & 1) ? __cosf(arg) : __sinf(arg);
            }
        }
        #pragma unroll
        for (int rr = 0; rr < 2; rr++) {
            const int nn = lr + rr * 64;
            const float4 v = *(const float4*)(W1 + (size_t)(n0+nn)*768 + d*256 + k0 + lc4*4);
            Bs[lc4*4+0][nn] = v.x; Bs[lc4*4+1][nn] = v.y;
            Bs[lc4*4+2][nn] = v.z; Bs[lc4*4+3][nn] = v.w;
        }
        __syncthreads();
        #pragma unroll
        for (int kk = 0; kk < 16; kk++) {
            float af[8], bf[8];
            *(float4*)&af[0] = *(const float4*)&As[kk][tm*8];
            *(float4*)&af[4] = *(const float4*)&As[kk][tm*8+4];
            *(float4*)&bf[0] = *(const float4*)&Bs[kk][tn*8];
            *(float4*)&bf[4] = *(const float4*)&Bs[kk][tn*8+4];
            #pragma unroll
            for (int i = 0; i < 8; i++)
                #pragma unroll
                for (int j = 0; j < 8; j++)
                    acc[i][j] = fmaf(af[i], bf[j], acc[i][j]);
        }
        __syncthreads();
    }
    #pragma unroll
    for (int i = 0; i < 8; i++) {
        const int row = ib + tm*8 + i;
        float* dst = g_table + ((size_t)(d*NTAB + row))*EN + n0 + tn*8;
        *(float4*)(dst)   = make_float4(acc[i][0], acc[i][1], acc[i][2], acc[i][3]);
        *(float4*)(dst+4) = make_float4(acc[i][4], acc[i][5], acc[i][6], acc[i][7]);
    }
}

// ---------------- hidden = relu(b1 + sum_d lerp(table_d, t_d)) ----------------
__global__ void bev_lookup(const float* __restrict__ b1) {
    int idx = blockIdx.x * blockDim.x + threadIdx.x;
    if (idx >= TOTC*QN*(EN/4)) return;
    int n4  = idx & 63;
    int row = idx >> 6;
    int cav = row >> 11;
    if (g_cav_local[cav] == 0 || g_batch_n[g_cav_batch[cav]] <= 1) return;
    float4 acc = *(const float4*)(b1 + n4*4);
    #pragma unroll
    for (int d = 0; d < 3; d++) {
        float tv = g_trans[(size_t)row*3 + d];
        float u  = tv * (float)(NTAB - 1);
        int i0 = (int)u;
        if (i0 < 0) i0 = 0;
        if (i0 > NTAB-2) i0 = NTAB-2;
        float w = u - (float)i0;
        const float* r = g_table + ((size_t)(d*NTAB + i0))*EN + n4*4;
        float4 a = *(const float4*)r;
        float4 b = *(const float4*)(r + EN);
        acc.x = fmaf(w, b.x - a.x, acc.x + a.x);
        acc.y = fmaf(w, b.y - a.y, acc.y + a.y);
        acc.z = fmaf(w, b.z - a.z, acc.z + a.z);
        acc.w = fmaf(w, b.w - a.w, acc.w + a.w);
    }
    float4 o = make_float4(fmaxf(acc.x,0.f), fmaxf(acc.y,0.f), fmaxf(acc.z,0.f), fmaxf(acc.w,0.f));
    *(float4*)(g_hidden + (size_t)row*EN + n4*4) = o;
}

// ================= bf16-split tensor-core GEMM (R4 core) =================
__device__ __forceinline__ uint32_t s2u(const void* p) {
    uint32_t a;
    asm("{ .reg .u64 t; cvta.to.shared.u64 t, %1; cvt.u32.u64 %0, t; }" : "=r"(a) : "l"(p));
    return a;
}
__device__ __forceinline__ void ldm4(uint32_t* f, uint32_t addr) {
    asm volatile("ldmatrix.sync.aligned.m8n8.x4.shared.b16 {%0,%1,%2,%3}, [%4];"
        : "=r"(f[0]),"=r"(f[1]),"=r"(f[2]),"=r"(f[3]) : "r"(addr));
}
__device__ __forceinline__ void mmabf(float* c, const uint32_t* a, const uint32_t* b) {
    asm volatile("mma.sync.aligned.m16n8k16.row.col.f32.bf16.bf16.f32 "
        "{%0,%1,%2,%3}, {%4,%5,%6,%7}, {%8,%9}, {%0,%1,%2,%3};"
        : "+f"(c[0]),"+f"(c[1]),"+f"(c[2]),"+f"(c[3])
        : "r"(a[0]),"r"(a[1]),"r"(a[2]),"r"(a[3]), "r"(b[0]),"r"(b[1]));
}
__device__ __forceinline__ uint32_t pkbf(float a, float b) {
    __nv_bfloat162 t = __floats2bfloat162_rn(a, b);
    return *(uint32_t*)&t;
}

#define TSTR 24
#define TSZ  (128*TSTR)

// MODE 1: kp = [x|hidden] @ wcat^T + bkp   (K=512)
// MODE 2: vp = x @ Wv^T + bv
// MODE 3: qp = ego[sel] @ Wq^T + bq
// MODE 4: ego[sel^1] = (n-1)*(ego[sel] + ctx @ Wo^T + bo)
template<int MODE, int KT>
__global__ __launch_bounds__(256) void mma_gemm(const float* __restrict__ W,
                                                const float* __restrict__ bias,
                                                const float* __restrict__ X,
                                                int sel) {
    __shared__ __align__(16) __nv_bfloat16 sm[2*4*TSZ];

    const int bm = blockIdx.x, bn = blockIdx.y;
    int cav = 0; float scale = 1.0f;
    if (MODE == 1 || MODE == 2) {
        cav = bm >> 4;
        if (g_cav_local[cav] == 0 || g_batch_n[g_cav_batch[cav]] <= 1) return;
    } else {
        int batch = bm >> 4;
        int n = g_batch_n[batch];
        if (n <= 1) return;
        scale = (float)(n - 1);
    }
    const int t    = threadIdx.x;
    const int lane = t & 31, wid = t >> 5;
    const int wm   = wid & 3, wn = wid >> 2;
    const int m0   = bm * 128, n0 = bn * 128;
    const int lrow = t >> 1;
    const int lk   = (t & 1) * 8;

    const int aoff = (wm*32 + (lane & 7) + ((lane >> 3) & 1) * 8) * TSTR + (lane >> 4) * 8;
    const int boff = (wn*64 + (lane & 7) + (lane >> 4) * 8) * TSTR + ((lane >> 3) & 1) * 8;

    const uint32_t smb = s2u(sm);

    float4 va0, va1, vw0, vw1;
    auto ld = [&](int kt) {
        const int k0 = kt * 16 + lk;
        const int arow = m0 + lrow;
        const float* s;
        if (MODE == 1) {
            if (k0 < 256) { int q = arow & (QN-1); s = X + (size_t)q*(TOTC*EN) + cav*EN + k0; }
            else            s = g_hidden + (size_t)arow*EN + (k0 - 256);
        } else if (MODE == 2) {
            int q = arow & (QN-1); s = X + (size_t)q*(TOTC*EN) + cav*EN + k0;
        } else if (MODE == 3) {
            s = g_ego[sel & 1] + (size_t)arow*EN + k0;
        } else {
            s = g_ctx + (size_t)arow*EN + k0;
        }
        va0 = *(const float4*)s;  va1 = *(const float4*)(s + 4);
        const float* ws = (MODE == 1) ? (g_wcat + (size_t)(n0 + lrow)*512 + k0)
                                      : (W      + (size_t)(n0 + lrow)*EN  + k0);
        vw0 = *(const float4*)ws; vw1 = *(const float4*)(ws + 4);
    };
    auto st = [&](int stage) {
        float a[8] = {va0.x,va0.y,va0.z,va0.w, va1.x,va1.y,va1.z,va1.w};
        float w[8] = {vw0.x,vw0.y,vw0.z,vw0.w, vw1.x,vw1.y,vw1.z,vw1.w};
        float ah[8], wh[8];
        uint32_t hi[4], lo[4];
        #pragma unroll
        for (int i = 0; i < 8; i++) ah[i] = __bfloat162float(__float2bfloat16_rn(a[i]));
        #pragma unroll
        for (int i = 0; i < 4; i++) {
            hi[i] = pkbf(ah[2*i], ah[2*i+1]);
            lo[i] = pkbf(a[2*i] - ah[2*i], a[2*i+1] - ah[2*i+1]);
        }
        const int eo = lrow * TSTR + lk;
        *(uint4*)&sm[(stage*4+0)*TSZ + eo] = make_uint4(hi[0],hi[1],hi[2],hi[3]);
        *(uint4*)&sm[(stage*4+1)*TSZ + eo] = make_uint4(lo[0],lo[1],lo[2],lo[3]);
        #pragma unroll
        for (int i = 0; i < 8; i++) wh[i] = __bfloat162float(__float2bfloat16_rn(w[i]));
        #pragma unroll
        for (int i = 0; i < 4; i++) {
            hi[i] = pkbf(wh[2*i], wh[2*i+1]);
            lo[i] = pkbf(w[2*i] - wh[2*i], w[2*i+1] - wh[2*i+1]);
        }
        *(uint4*)&sm[(stage*4+2)*TSZ + eo] = make_uint4(hi[0],hi[1],hi[2],hi[3]);
        *(uint4*)&sm[(stage*4+3)*TSZ + eo] = make_uint4(lo[0],lo[1],lo[2],lo[3]);
    };

    float acc[2][8][4] = {};

    ld(0); st(0);
    __syncthreads();
    for (int kt = 0; kt < KT; kt++) {
        if (kt + 1 < KT) ld(kt + 1);
        const int stage = kt & 1;
        const uint32_t bA = smb + (stage*4+0)*TSZ*2 + aoff*2;
        const uint32_t bAl= smb + (stage*4+1)*TSZ*2 + aoff*2;
        const uint32_t bW = smb + (stage*4+2)*TSZ*2 + boff*2;
        const uint32_t bWl= smb + (stage*4+3)*TSZ*2 + boff*2;

        uint32_t Ahi[2][4], Alo[2][4];
        #pragma unroll
        for (int ms = 0; ms < 2; ms++) {
            ldm4(Ahi[ms], bA  + ms*16*TSTR*2);
            ldm4(Alo[ms], bAl + ms*16*TSTR*2);
        }
        #pragma unroll
        for (int np = 0; np < 4; np++) {
            uint32_t Bhi[4], Blo[4];
            ldm4(Bhi, bW  + np*16*TSTR*2);
            ldm4(Blo, bWl + np*16*TSTR*2);
            #pragma unroll
            for (int ms = 0; ms < 2; ms++) {
                mmabf(acc[ms][2*np],   Ahi[ms], Bhi);
                mmabf(acc[ms][2*np+1], Ahi[ms], Bhi+2);
                mmabf(acc[ms][2*np],   Alo[ms], Bhi);
                mmabf(acc[ms][2*np+1], Alo[ms], Bhi+2);
                mmabf(acc[ms][2*np],   Ahi[ms], Blo);
                mmabf(acc[ms][2*np+1], Ahi[ms], Blo+2);
            }
        }
        if (kt + 1 < KT) st(stage ^ 1);
        __syncthreads();
    }

    // epilogue
    const float* bptr = (MODE == 1) ? g_bkp : bias;
    #pragma unroll
    for (int ms = 0; ms < 2; ms++) {
        const int row = m0 + wm*32 + ms*16 + (lane >> 2);
        #pragma unroll
        for (int ns = 0; ns < 8; ns++) {
            const int col = n0 + wn*64 + ns*8 + (lane & 3)*2;
            const float2 bv = *(const float2*)(bptr + col);
            #pragma unroll
            for (int h = 0; h < 2; h++) {
                const int r = row + h*8;
                float v0 = acc[ms][ns][2*h]   + bv.x;
                float v1 = acc[ms][ns][2*h+1] + bv.y;
                float* dst;
                if (MODE == 1)      dst = g_kp + (size_t)r*EN + col;
                else if (MODE == 2) dst = g_vp + (size_t)r*EN + col;
                else if (MODE == 3) dst = g_qp + (size_t)r*EN + col;
                else {
                    const float2 er = *(const float2*)(g_ego[sel & 1] + (size_t)r*EN + col);
                    v0 = scale * (er.x + v0);
                    v1 = scale * (er.y + v1);
                    dst = g_ego[(sel ^ 1) & 1] + (size_t)r*EN + col;
                }
                *(float2*)dst = make_float2(v0, v1);
            }
        }
    }
}

// ---------------- degenerate attention ----------------
__global__ void attn_kernel() {
    int w = (blockIdx.x * blockDim.x + threadIdx.x) >> 5;
    int lane = threadIdx.x & 31;
    if (w >= NB * QN * NH) return;
    int h  = w & 7;
    int bq = w >> 3;
    int b  = bq >> 11;
    int q  = bq & (QN - 1);
    int n  = g_batch_n[b];
    if (n <= 1) return;
    int nm  = n - 1;
    int off = g_batch_off[b];
    int col = h * 32 + lane;

    float qv = g_qp[(size_t)bq*EN + col];
    float sc[LMAXC - 1];
    for (int m = 0; m < nm; m++) {
        int c = off + 1 + m;
        float p = qv * g_kp[(size_t)(c*QN + q)*EN + col];
        #pragma unroll
        for (int o = 16; o; o >>= 1) p += __shfl_xor_sync(0xffffffffu, p, o);
        sc[m] = p * 0.17677669529663687f;
    }
    float mx = -1e30f;
    for (int m = 0; m < nm; m++) mx = fmaxf(mx, sc[m]);
    float s = 0.0f, wt[LMAXC - 1];
    for (int m = 0; m < nm; m++) { wt[m] = __expf(sc[m] - mx); s += wt[m]; }
    float inv = 1.0f / s;
    float ctx = 0.0f;
    for (int m = 0; m < nm; m++) {
        int c = off + 1 + m;
        ctx = fmaf(wt[m] * inv, g_vp[(size_t)(c*QN + q)*EN + col], ctx);
    }
    g_ctx[(size_t)bq*EN + col] = ctx;
}

// ---------------- final merge ----------------
__global__ void out_kernel(const float* __restrict__ x, float* __restrict__ out, int fin) {
    int idx = blockIdx.x * blockDim.x + threadIdx.x;
    if (idx >= QN * TOTC * (EN/4)) return;
    int e4 = idx & 63;
    int qc = idx >> 6;
    int c  = qc % TOTC;
    int q  = qc / TOTC;
    int b  = g_cav_batch[c], l = g_cav_local[c];
    float4 v;
    if (l == 0 && g_batch_n[b] > 1)
        v = *(const float4*)(g_ego[fin & 1] + (size_t)(b*QN + q)*EN + e4*4);
    else
        v = *(const float4*)(x + (size_t)idx*4);
    *(float4*)(out + (size_t)idx*4) = v;
}

// ---------------- launch (fork-join multi-stream) ----------------
extern "C" void kernel_launch(void* const* d_in, const int* in_sizes, int n_in,
                              void* d_out, int out_size) {
    const float*     x    = (const float*)d_in[0];
    const float*     rp   = (const float*)d_in[1];
    const float*     ptm  = (const float*)d_in[2];
    const long long* rl   = (const long long*)d_in[3];
    const float*     in_w = (const float*)d_in[4];
    const float*     in_b = (const float*)d_in[5];
    const float*     ow   = (const float*)d_in[6];
    const float*     ob   = (const float*)d_in[7];
    const float*     w1   = (const float*)d_in[8];
    const float*     b1   = (const float*)d_in[9];
    const float*     w2   = (const float*)d_in[10];
    const float*     b2   = (const float*)d_in[11];
    float* out = (float*)d_out;

    static cudaStream_t sB = nullptr, sC = nullptr;
    static cudaEvent_t  ev0 = nullptr, evB = nullptr, evC = nullptr;
    if (sB == nullptr) {
        cudaStreamCreateWithFlags(&sB, cudaStreamNonBlocking);
        cudaStreamCreateWithFlags(&sC, cudaStreamNonBlocking);
        cudaEventCreateWithFlags(&ev0, cudaEventDisableTiming);
        cudaEventCreateWithFlags(&evB, cudaEventDisableTiming);
        cudaEventCreateWithFlags(&evC, cudaEventDisableTiming);
    }

    dim3 gcav(TOTC*QN/128, 2);
    dim3 gego(NB*QN/128, 2);

    // main stream: setup, then fork
    setup_kernel<<<1, 256>>>(rl);
    cudaEventRecord(ev0, 0);

    // stream B: vp GEMM + ego init + qp1 (independent of table/wkk chain)
    cudaStreamWaitEvent(sB, ev0, 0);
    mma_gemm<2,16><<<gcav, 256, 0, sB>>>(in_w + 512*EN, in_b + 512, x, 0);   // vp
    ego_init_kernel<<<(NB*QN*(EN/4) + 255)/256, 256, 0, sB>>>(x);
    mma_gemm<3,16><<<gego, 256, 0, sB>>>(in_w, in_b, x, 0);                  // qp (iter 1)
    cudaEventRecord(evB, sB);

    // stream C: wkk (weights only)
    cudaStreamWaitEvent(sC, ev0, 0);
    wkk_kernel<<<EN, EN, 0, sC>>>(in_w, in_b, w2, b2);
    cudaEventRecord(evC, sC);

    // main stream: trans -> table -> bev_lookup -> (join wkk) kp
    trans_kernel<<<(TOTC*QN + 255)/256, 256>>>(rp, ptm);
    table_kernel<<<dim3(3*NTAB/128, 2), 256>>>(w1);
    bev_lookup<<<(TOTC*QN*(EN/4) + 255)/256, 256>>>(b1);
    cudaStreamWaitEvent(0, evC, 0);
    mma_gemm<1,32><<<gcav, 256>>>(nullptr, nullptr, x, 0);                   // kp (K=512)

    // join stream B, then serial attention iterations
    cudaStreamWaitEvent(0, evB, 0);
    attn_kernel<<<NB*QN*NH*32/256, 256>>>();                                 // ctx (iter 1)
    mma_gemm<4,16><<<gego, 256>>>(ow, ob, x, 0);                             // ego -> ego[1]
    mma_gemm<3,16><<<gego, 256>>>(in_w, in_b, x, 1);                         // qp (iter 2)
    attn_kernel<<<NB*QN*NH*32/256, 256>>>();                                 // ctx (iter 2)
    mma_gemm<4,16><<<gego, 256>>>(ow, ob, x, 1);                             // ego -> ego[0]
    out_kernel<<<(QN*TOTC*(EN/4) + 255)/256, 256>>>(x, out, 0);
}

// round 9
// speedup vs baseline: 1.1433x; 1.0009x over previous
#include <cuda_runtime.h>
#include <cuda_bf16.h>
#include <cstdint>

#define QN    2048
#define EN    256
#define TOTC  40
#define NB    8
#define LMAXC 5
#define NH    8
#define NTAB  2048

// ---------------- scratch ----------------
__device__ float g_trans [TOTC*QN*3];
__device__ float g_hidden[TOTC*QN*EN];
__device__ float g_kp    [TOTC*QN*EN];
__device__ float g_vp    [TOTC*QN*EN];
__device__ float g_ego   [2][NB*QN*EN];
__device__ float g_qp    [NB*QN*EN];
__device__ float g_ctx   [NB*QN*EN];
__device__ float g_table [3*NTAB*EN];
__device__ float g_wcat  [EN*512];
__device__ float g_bkp   [EN];
__device__ float g_freq  [EN];
__device__ int   g_cav_batch[TOTC];
__device__ int   g_cav_local[TOTC];
__device__ int   g_batch_n  [NB];
__device__ int   g_batch_off[NB];

// ---------------- setup ----------------
__global__ void setup_kernel(const long long* __restrict__ rl64) {
    int t = threadIdx.x;
    if (t == 0) {
        bool ok64 = true;
        for (int b = 0; b < NB; b++) {
            long long v = rl64[b];
            if (v < 1 || v > LMAXC) ok64 = false;
        }
        const int* rl32 = (const int*)rl64;
        int acc = 0;
        for (int c = 0; c < TOTC; c++) { g_cav_batch[c] = 0; g_cav_local[c] = 0; }
        for (int b = 0; b < NB; b++) {
            int n = ok64 ? (int)rl64[b] : rl32[b];
            if (n < 1) n = 1;
            if (n > LMAXC) n = LMAXC;
            g_batch_n[b] = n; g_batch_off[b] = acc;
            for (int l = 0; l < n; l++) {
                int c = acc + l;
                if (c < TOTC) { g_cav_batch[c] = b; g_cav_local[c] = l; }
            }
            acc += n;
        }
    }
    for (int j = t; j < EN; j += blockDim.x) {
        float ex = (2.0f * (float)(j >> 1)) / (float)EN;
        g_freq[j] = 6.283185307179586f * expf(-ex * 9.210340371976184f);
    }
}

// ---------------- trans ----------------
__global__ void trans_kernel(const float* __restrict__ rp, const float* __restrict__ ptm) {
    int idx = blockIdx.x * blockDim.x + threadIdx.x;
    if (idx >= TOTC * QN) return;
    int c = idx / QN;
    int b = g_cav_batch[c], l = g_cav_local[c];
    float r0 = rp[idx*3+0] * 281.6f - 140.8f;
    float r1 = rp[idx*3+1] *  80.0f -  40.0f;
    float r2 = rp[idx*3+2] *   4.0f -   3.0f;
    const float* T = ptm + (size_t)((b * LMAXC + l) * LMAXC) * 16;
    #pragma unroll
    for (int i = 0; i < 3; i++) {
        float z = fmaf(T[i*4+0], r0, fmaf(T[i*4+1], r1, fmaf(T[i*4+2], r2, T[i*4+3])));
        g_trans[idx*3+i] = 1.0f / (1.0f + expf(-z));
    }
}

// ---------------- ego init ----------------
__global__ void ego_init_kernel(const float* __restrict__ x) {
    int idx = blockIdx.x * blockDim.x + threadIdx.x;
    if (idx >= NB * QN * (EN/4)) return;
    int e4 = idx & 63;
    int rq = idx >> 6;
    int b  = rq >> 11;
    int q  = rq & (QN-1);
    int off = g_batch_off[b];
    float4 v = *(const float4*)(x + (size_t)q*(TOTC*EN) + off*EN + e4*4);
    *(float4*)(&g_ego[0][(size_t)rq*EN + e4*4]) = v;
}

// ---------------- wcat = [Wk | Wk@W2], bkp = bk + Wk@b2 ----------------
__global__ void wkk_kernel(const float* __restrict__ in_w, const float* __restrict__ in_b,
                           const float* __restrict__ w2,   const float* __restrict__ b2) {
    __shared__ float sWk[EN];
    __shared__ float red[EN];
    int n = blockIdx.x, j = threadIdx.x;
    sWk[j] = in_w[(size_t)(EN + n)*EN + j];
    __syncthreads();
    float a0 = 0.f, a1 = 0.f, a2 = 0.f, a3 = 0.f;
    #pragma unroll 4
    for (int m = 0; m < EN; m += 4) {
        a0 = fmaf(sWk[m+0], w2[(size_t)(m+0)*EN + j], a0);
        a1 = fmaf(sWk[m+1], w2[(size_t)(m+1)*EN + j], a1);
        a2 = fmaf(sWk[m+2], w2[(size_t)(m+2)*EN + j], a2);
        a3 = fmaf(sWk[m+3], w2[(size_t)(m+3)*EN + j], a3);
    }
    float acc = (a0 + a1) + (a2 + a3);
    g_wcat[(size_t)n*512 + j]      = sWk[j];
    g_wcat[(size_t)n*512 + EN + j] = acc;
    red[j] = sWk[j] * b2[j];
    __syncthreads();
    for (int s = 128; s > 0; s >>= 1) {
        if (j < s) red[j] += red[j + s];
        __syncthreads();
    }
    if (j == 0) g_bkp[n] = in_b[EN + n] + red[0];
}

// ---------------- table GEMM (fp32 SIMT, small) ----------------
__global__ __launch_bounds__(256) void table_kernel(const float* __restrict__ W1) {
    const int bm = blockIdx.x, bn = blockIdx.y;
    const int d  = bm / (NTAB/128);
    const int ib = (bm % (NTAB/128)) * 128;
    __shared__ float As[16][132];
    __shared__ float Bs[16][132];
    __shared__ float fr[EN];
    const int t  = threadIdx.x;
    const int tm = t >> 4, tn = t & 15;
    const int lr = t >> 2, lc4 = t & 3;
    const int n0 = bn * 128;
    fr[t] = g_freq[t & (EN-1)];
    __syncthreads();
    float acc[8][8] = {};
    const float inv = 1.0f / (float)(NTAB - 1);
    for (int kt = 0; kt < 16; kt++) {
        const int k0 = kt * 16;
        #pragma unroll
        for (int rr = 0; rr < 2; rr++) {
            const int m = lr + rr * 64;
            const float tv = (float)(ib + m) * inv;
            #pragma unroll
            for (int i = 0; i < 4; i++) {
                const int kk = lc4*4 + i, j = k0 + kk;
                const float arg = tv * fr[j];
                As[kk][m] = (j & 1) ? __cosf(arg) : __sinf(arg);
            }
        }
        #pragma unroll
        for (int rr = 0; rr < 2; rr++) {
            const int nn = lr + rr * 64;
            const float4 v = *(const float4*)(W1 + (size_t)(n0+nn)*768 + d*256 + k0 + lc4*4);
            Bs[lc4*4+0][nn] = v.x; Bs[lc4*4+1][nn] = v.y;
            Bs[lc4*4+2][nn] = v.z; Bs[lc4*4+3][nn] = v.w;
        }
        __syncthreads();
        #pragma unroll
        for (int kk = 0; kk < 16; kk++) {
            float af[8], bf[8];
            *(float4*)&af[0] = *(const float4*)&As[kk][tm*8];
            *(float4*)&af[4] = *(const float4*)&As[kk][tm*8+4];
            *(float4*)&bf[0] = *(const float4*)&Bs[kk][tn*8];
            *(float4*)&bf[4] = *(const float4*)&Bs[kk][tn*8+4];
            #pragma unroll
            for (int i = 0; i < 8; i++)
                #pragma unroll
                for (int j = 0; j < 8; j++)
                    acc[i][j] = fmaf(af[i], bf[j], acc[i][j]);
        }
        __syncthreads();
    }
    #pragma unroll
    for (int i = 0; i < 8; i++) {
        const int row = ib + tm*8 + i;
        float* dst = g_table + ((size_t)(d*NTAB + row))*EN + n0 + tn*8;
        *(float4*)(dst)   = make_float4(acc[i][0], acc[i][1], acc[i][2], acc[i][3]);
        *(float4*)(dst+4) = make_float4(acc[i][4], acc[i][5], acc[i][6], acc[i][7]);
    }
}

// ---------------- hidden = relu(b1 + sum_d lerp(table_d, t_d)) ----------------
__global__ void bev_lookup(const float* __restrict__ b1) {
    int idx = blockIdx.x * blockDim.x + threadIdx.x;
    if (idx >= TOTC*QN*(EN/4)) return;
    int n4  = idx & 63;
    int row = idx >> 6;
    int cav = row >> 11;
    if (g_cav_local[cav] == 0 || g_batch_n[g_cav_batch[cav]] <= 1) return;
    float4 acc = *(const float4*)(b1 + n4*4);
    #pragma unroll
    for (int d = 0; d < 3; d++) {
        float tv = g_trans[(size_t)row*3 + d];
        float u  = tv * (float)(NTAB - 1);
        int i0 = (int)u;
        if (i0 < 0) i0 = 0;
        if (i0 > NTAB-2) i0 = NTAB-2;
        float w = u - (float)i0;
        const float* r = g_table + ((size_t)(d*NTAB + i0))*EN + n4*4;
        float4 a = *(const float4*)r;
        float4 b = *(const float4*)(r + EN);
        acc.x = fmaf(w, b.x - a.x, acc.x + a.x);
        acc.y = fmaf(w, b.y - a.y, acc.y + a.y);
        acc.z = fmaf(w, b.z - a.z, acc.z + a.z);
        acc.w = fmaf(w, b.w - a.w, acc.w + a.w);
    }
    float4 o = make_float4(fmaxf(acc.x,0.f), fmaxf(acc.y,0.f), fmaxf(acc.z,0.f), fmaxf(acc.w,0.f));
    *(float4*)(g_hidden + (size_t)row*EN + n4*4) = o;
}

// ================= bf16-split tensor-core GEMM =================
__device__ __forceinline__ uint32_t s2u(const void* p) {
    uint32_t a;
    asm("{ .reg .u64 t; cvta.to.shared.u64 t, %1; cvt.u32.u64 %0, t; }" : "=r"(a) : "l"(p));
    return a;
}
__device__ __forceinline__ void ldm4(uint32_t* f, uint32_t addr) {
    asm volatile("ldmatrix.sync.aligned.m8n8.x4.shared.b16 {%0,%1,%2,%3}, [%4];"
        : "=r"(f[0]),"=r"(f[1]),"=r"(f[2]),"=r"(f[3]) : "r"(addr));
}
__device__ __forceinline__ void mmabf(float* c, const uint32_t* a, const uint32_t* b) {
    asm volatile("mma.sync.aligned.m16n8k16.row.col.f32.bf16.bf16.f32 "
        "{%0,%1,%2,%3}, {%4,%5,%6,%7}, {%8,%9}, {%0,%1,%2,%3};"
        : "+f"(c[0]),"+f"(c[1]),"+f"(c[2]),"+f"(c[3])
        : "r"(a[0]),"r"(a[1]),"r"(a[2]),"r"(a[3]), "r"(b[0]),"r"(b[1]));
}
__device__ __forceinline__ uint32_t pkbf(float a, float b) {
    __nv_bfloat162 t = __floats2bfloat162_rn(a, b);
    return *(uint32_t*)&t;
}

#define TSTR 24
#define TSZ  (128*TSTR)

// MODE 1: kp = [x|hidden] @ wcat^T + bkp   (K=512)
// MODE 2: vp = x @ Wv^T + bv
// MODE 3: qp = ego[sel] @ Wq^T + bq
// MODE 4: ego[sel^1] = (n-1)*(ego[sel] + ctx @ Wo^T + bo)
// MODE 5: out[(q*TOTC+off_b)*EN+col] = (n-1)*(ego[sel] + ctx @ Wo^T + bo)   (final)
template<int MODE, int KT>
__global__ __launch_bounds__(256) void mma_gemm(const float* __restrict__ W,
                                                const float* __restrict__ bias,
                                                const float* __restrict__ X,
                                                float* __restrict__ OUT,
                                                int sel) {
    __shared__ __align__(16) __nv_bfloat16 sm[2*4*TSZ];

    const int bm = blockIdx.x, bn = blockIdx.y;
    int cav = 0; float scale = 1.0f;
    int boff = 0;
    if (MODE == 1 || MODE == 2) {
        cav = bm >> 4;
        if (g_cav_local[cav] == 0 || g_batch_n[g_cav_batch[cav]] <= 1) return;
    } else {
        int batch = bm >> 4;
        int n = g_batch_n[batch];
        if (n <= 1) return;
        scale = (float)(n - 1);
        boff = g_batch_off[batch];
    }
    const int t    = threadIdx.x;
    const int lane = t & 31, wid = t >> 5;
    const int wm   = wid & 3, wn = wid >> 2;
    const int m0   = bm * 128, n0 = bn * 128;
    const int lrow = t >> 1;
    const int lk   = (t & 1) * 8;

    const int aoff  = (wm*32 + (lane & 7) + ((lane >> 3) & 1) * 8) * TSTR + (lane >> 4) * 8;
    const int boff2 = (wn*64 + (lane & 7) + (lane >> 4) * 8) * TSTR + ((lane >> 3) & 1) * 8;

    const uint32_t smb = s2u(sm);

    float4 va0, va1, vw0, vw1;
    auto ld = [&](int kt) {
        const int k0 = kt * 16 + lk;
        const int arow = m0 + lrow;
        const float* s;
        if (MODE == 1) {
            if (k0 < 256) { int q = arow & (QN-1); s = X + (size_t)q*(TOTC*EN) + cav*EN + k0; }
            else            s = g_hidden + (size_t)arow*EN + (k0 - 256);
        } else if (MODE == 2) {
            int q = arow & (QN-1); s = X + (size_t)q*(TOTC*EN) + cav*EN + k0;
        } else if (MODE == 3) {
            s = g_ego[sel & 1] + (size_t)arow*EN + k0;
        } else {
            s = g_ctx + (size_t)arow*EN + k0;
        }
        va0 = *(const float4*)s;  va1 = *(const float4*)(s + 4);
        const float* ws = (MODE == 1) ? (g_wcat + (size_t)(n0 + lrow)*512 + k0)
                                      : (W      + (size_t)(n0 + lrow)*EN  + k0);
        vw0 = *(const float4*)ws; vw1 = *(const float4*)(ws + 4);
    };
    auto st = [&](int stage) {
        float a[8] = {va0.x,va0.y,va0.z,va0.w, va1.x,va1.y,va1.z,va1.w};
        float w[8] = {vw0.x,vw0.y,vw0.z,vw0.w, vw1.x,vw1.y,vw1.z,vw1.w};
        float ah[8], wh[8];
        uint32_t hi[4], lo[4];
        #pragma unroll
        for (int i = 0; i < 8; i++) ah[i] = __bfloat162float(__float2bfloat16_rn(a[i]));
        #pragma unroll
        for (int i = 0; i < 4; i++) {
            hi[i] = pkbf(ah[2*i], ah[2*i+1]);
            lo[i] = pkbf(a[2*i] - ah[2*i], a[2*i+1] - ah[2*i+1]);
        }
        const int eo = lrow * TSTR + lk;
        *(uint4*)&sm[(stage*4+0)*TSZ + eo] = make_uint4(hi[0],hi[1],hi[2],hi[3]);
        *(uint4*)&sm[(stage*4+1)*TSZ + eo] = make_uint4(lo[0],lo[1],lo[2],lo[3]);
        #pragma unroll
        for (int i = 0; i < 8; i++) wh[i] = __bfloat162float(__float2bfloat16_rn(w[i]));
        #pragma unroll
        for (int i = 0; i < 4; i++) {
            hi[i] = pkbf(wh[2*i], wh[2*i+1]);
            lo[i] = pkbf(w[2*i] - wh[2*i], w[2*i+1] - wh[2*i+1]);
        }
        *(uint4*)&sm[(stage*4+2)*TSZ + eo] = make_uint4(hi[0],hi[1],hi[2],hi[3]);
        *(uint4*)&sm[(stage*4+3)*TSZ + eo] = make_uint4(lo[0],lo[1],lo[2],lo[3]);
    };

    float acc[2][8][4] = {};

    ld(0); st(0);
    __syncthreads();
    for (int kt = 0; kt < KT; kt++) {
        if (kt + 1 < KT) ld(kt + 1);
        const int stage = kt & 1;
        const uint32_t bA = smb + (stage*4+0)*TSZ*2 + aoff*2;
        const uint32_t bAl= smb + (stage*4+1)*TSZ*2 + aoff*2;
        const uint32_t bW = smb + (stage*4+2)*TSZ*2 + boff2*2;
        const uint32_t bWl= smb + (stage*4+3)*TSZ*2 + boff2*2;

        uint32_t Ahi[2][4], Alo[2][4];
        #pragma unroll
        for (int ms = 0; ms < 2; ms++) {
            ldm4(Ahi[ms], bA  + ms*16*TSTR*2);
            ldm4(Alo[ms], bAl + ms*16*TSTR*2);
        }
        // groups of 2 n-pairs, pass-major ordering (acc RAW distance = 8)
        #pragma unroll
        for (int g = 0; g < 2; g++) {
            uint32_t Bhi[2][4], Blo[2][4];
            #pragma unroll
            for (int j = 0; j < 2; j++) {
                ldm4(Bhi[j], bW  + (2*g+j)*16*TSTR*2);
                ldm4(Blo[j], bWl + (2*g+j)*16*TSTR*2);
            }
            #pragma unroll
            for (int j = 0; j < 2; j++)
                #pragma unroll
                for (int ms = 0; ms < 2; ms++) {
                    mmabf(acc[ms][2*(2*g+j)],   Ahi[ms], Bhi[j]);
                    mmabf(acc[ms][2*(2*g+j)+1], Ahi[ms], Bhi[j]+2);
                }
            #pragma unroll
            for (int j = 0; j < 2; j++)
                #pragma unroll
                for (int ms = 0; ms < 2; ms++) {
                    mmabf(acc[ms][2*(2*g+j)],   Alo[ms], Bhi[j]);
                    mmabf(acc[ms][2*(2*g+j)+1], Alo[ms], Bhi[j]+2);
                }
            #pragma unroll
            for (int j = 0; j < 2; j++)
                #pragma unroll
                for (int ms = 0; ms < 2; ms++) {
                    mmabf(acc[ms][2*(2*g+j)],   Ahi[ms], Blo[j]);
                    mmabf(acc[ms][2*(2*g+j)+1], Ahi[ms], Blo[j]+2);
                }
        }
        if (kt + 1 < KT) st(stage ^ 1);
        __syncthreads();
    }

    // epilogue
    const float* bptr = (MODE == 1) ? g_bkp : bias;
    #pragma unroll
    for (int ms = 0; ms < 2; ms++) {
        const int row = m0 + wm*32 + ms*16 + (lane >> 2);
        #pragma unroll
        for (int ns = 0; ns < 8; ns++) {
            const int col = n0 + wn*64 + ns*8 + (lane & 3)*2;
            const float2 bv = *(const float2*)(bptr + col);
            #pragma unroll
            for (int h = 0; h < 2; h++) {
                const int r = row + h*8;
                float v0 = acc[ms][ns][2*h]   + bv.x;
                float v1 = acc[ms][ns][2*h+1] + bv.y;
                float* dst;
                if (MODE == 1)      dst = g_kp + (size_t)r*EN + col;
                else if (MODE == 2) dst = g_vp + (size_t)r*EN + col;
                else if (MODE == 3) dst = g_qp + (size_t)r*EN + col;
                else {
                    const float2 er = *(const float2*)(g_ego[sel & 1] + (size_t)r*EN + col);
                    v0 = scale * (er.x + v0);
                    v1 = scale * (er.y + v1);
                    if (MODE == 4) {
                        dst = g_ego[(sel ^ 1) & 1] + (size_t)r*EN + col;
                    } else {
                        int q = r & (QN - 1);
                        dst = OUT + ((size_t)q*TOTC + boff)*EN + col;
                    }
                }
                *(float2*)dst = make_float2(v0, v1);
            }
        }
    }
}

// ---------------- degenerate attention ----------------
__global__ void attn_kernel() {
    int w = (blockIdx.x * blockDim.x + threadIdx.x) >> 5;
    int lane = threadIdx.x & 31;
    if (w >= NB * QN * NH) return;
    int h  = w & 7;
    int bq = w >> 3;
    int b  = bq >> 11;
    int q  = bq & (QN - 1);
    int n  = g_batch_n[b];
    if (n <= 1) return;
    int nm  = n - 1;
    int off = g_batch_off[b];
    int col = h * 32 + lane;

    float qv = g_qp[(size_t)bq*EN + col];
    float sc[LMAXC - 1];
    for (int m = 0; m < nm; m++) {
        int c = off + 1 + m;
        float p = qv * g_kp[(size_t)(c*QN + q)*EN + col];
        #pragma unroll
        for (int o = 16; o; o >>= 1) p += __shfl_xor_sync(0xffffffffu, p, o);
        sc[m] = p * 0.17677669529663687f;
    }
    float mx = -1e30f;
    for (int m = 0; m < nm; m++) mx = fmaxf(mx, sc[m]);
    float s = 0.0f, wt[LMAXC - 1];
    for (int m = 0; m < nm; m++) { wt[m] = __expf(sc[m] - mx); s += wt[m]; }
    float inv = 1.0f / s;
    float ctx = 0.0f;
    for (int m = 0; m < nm; m++) {
        int c = off + 1 + m;
        ctx = fmaf(wt[m] * inv, g_vp[(size_t)(c*QN + q)*EN + col], ctx);
    }
    g_ctx[(size_t)bq*EN + col] = ctx;
}

// ---------------- launch (fork-join multi-stream) ----------------
extern "C" void kernel_launch(void* const* d_in, const int* in_sizes, int n_in,
                              void* d_out, int out_size) {
    const float*     x    = (const float*)d_in[0];
    const float*     rp   = (const float*)d_in[1];
    const float*     ptm  = (const float*)d_in[2];
    const long long* rl   = (const long long*)d_in[3];
    const float*     in_w = (const float*)d_in[4];
    const float*     in_b = (const float*)d_in[5];
    const float*     ow   = (const float*)d_in[6];
    const float*     ob   = (const float*)d_in[7];
    const float*     w1   = (const float*)d_in[8];
    const float*     b1   = (const float*)d_in[9];
    const float*     w2   = (const float*)d_in[10];
    const float*     b2   = (const float*)d_in[11];
    float* out = (float*)d_out;

    static cudaStream_t sB = nullptr, sC = nullptr, sD = nullptr;
    static cudaEvent_t  ev0 = nullptr, evB = nullptr, evC = nullptr, evX = nullptr;
    if (sB == nullptr) {
        cudaStreamCreateWithFlags(&sB, cudaStreamNonBlocking);
        cudaStreamCreateWithFlags(&sC, cudaStreamNonBlocking);
        cudaStreamCreateWithFlags(&sD, cudaStreamNonBlocking);
        cudaEventCreateWithFlags(&ev0, cudaEventDisableTiming);
        cudaEventCreateWithFlags(&evB, cudaEventDisableTiming);
        cudaEventCreateWithFlags(&evC, cudaEventDisableTiming);
        cudaEventCreateWithFlags(&evX, cudaEventDisableTiming);
    }

    dim3 gcav(TOTC*QN/128, 2);
    dim3 gego(NB*QN/128, 2);

    // main stream: setup first, then fork ALL side streams off ev0
    setup_kernel<<<1, 256>>>(rl);
    cudaEventRecord(ev0, 0);

    // stream D: bulk copy x -> out (properly forked from capture origin)
    cudaStreamWaitEvent(sD, ev0, 0);
    cudaMemcpyAsync(out, x, (size_t)QN*TOTC*EN*sizeof(float),
                    cudaMemcpyDeviceToDevice, sD);
    cudaEventRecord(evX, sD);

    // stream B: vp GEMM + ego init + qp1
    cudaStreamWaitEvent(sB, ev0, 0);
    mma_gemm<2,16><<<gcav, 256, 0, sB>>>(in_w + 512*EN, in_b + 512, x, out, 0);  // vp
    ego_init_kernel<<<(NB*QN*(EN/4) + 255)/256, 256, 0, sB>>>(x);
    mma_gemm<3,16><<<gego, 256, 0, sB>>>(in_w, in_b, x, out, 0);                 // qp (iter 1)
    cudaEventRecord(evB, sB);

    // stream C: wkk
    cudaStreamWaitEvent(sC, ev0, 0);
    wkk_kernel<<<EN, EN, 0, sC>>>(in_w, in_b, w2, b2);
    cudaEventRecord(evC, sC);

    // main stream: trans -> table -> bev_lookup -> (join wkk) kp
    trans_kernel<<<(TOTC*QN + 255)/256, 256>>>(rp, ptm);
    table_kernel<<<dim3(3*NTAB/128, 2), 256>>>(w1);
    bev_lookup<<<(TOTC*QN*(EN/4) + 255)/256, 256>>>(b1);
    cudaStreamWaitEvent(0, evC, 0);
    mma_gemm<1,32><<<gcav, 256>>>(nullptr, nullptr, x, out, 0);                  // kp (K=512)

    // join stream B, then serial attention iterations
    cudaStreamWaitEvent(0, evB, 0);
    attn_kernel<<<NB*QN*NH*32/256, 256>>>();                                     // ctx (iter 1)
    mma_gemm<4,16><<<gego, 256>>>(ow, ob, x, out, 0);                            // ego -> ego[1]
    mma_gemm<3,16><<<gego, 256>>>(in_w, in_b, x, out, 1);                        // qp (iter 2)
    attn_kernel<<<NB*QN*NH*32/256, 256>>>();                                     // ctx (iter 2)
    cudaStreamWaitEvent(0, evX, 0);
    mma_gemm<5,16><<<gego, 256>>>(ow, ob, x, out, 1);                            // final ego -> out
}

// round 10
// speedup vs baseline: 1.2181x; 1.0654x over previous
#include <cuda_runtime.h>
#include <cuda_bf16.h>
#include <cstdint>

#define QN    2048
#define EN    256
#define TOTC  40
#define NB    8
#define LMAXC 5
#define NH    8
#define NTAB  2048

// ---------------- scratch ----------------
__device__ float g_trans [TOTC*QN*3];
__device__ float g_hidden[TOTC*QN*EN];
__device__ float g_kp    [TOTC*QN*EN];
__device__ float g_vp    [TOTC*QN*EN];
__device__ float g_qpA   [NB*QN*EN];
__device__ float g_qpB   [NB*QN*EN];
__device__ float g_ctx   [NB*QN*EN];
__device__ float g_table [3*NTAB*EN];
__device__ float g_trig  [NTAB*EN];
__device__ float g_wcat  [EN*512];
__device__ float g_bkp   [EN];
__device__ float g_wowq  [EN*EN];
__device__ float g_bqo   [EN];
__device__ float g_freq  [EN];
__device__ int   g_cav_batch[TOTC];
__device__ int   g_cav_local[TOTC];
__device__ int   g_batch_n  [NB];
__device__ int   g_batch_off[NB];

// ---------------- setup ----------------
__global__ void setup_kernel(const long long* __restrict__ rl64) {
    int t = threadIdx.x;
    if (t == 0) {
        bool ok64 = true;
        for (int b = 0; b < NB; b++) {
            long long v = rl64[b];
            if (v < 1 || v > LMAXC) ok64 = false;
        }
        const int* rl32 = (const int*)rl64;
        int acc = 0;
        for (int c = 0; c < TOTC; c++) { g_cav_batch[c] = 0; g_cav_local[c] = 0; }
        for (int b = 0; b < NB; b++) {
            int n = ok64 ? (int)rl64[b] : rl32[b];
            if (n < 1) n = 1;
            if (n > LMAXC) n = LMAXC;
            g_batch_n[b] = n; g_batch_off[b] = acc;
            for (int l = 0; l < n; l++) {
                int c = acc + l;
                if (c < TOTC) { g_cav_batch[c] = b; g_cav_local[c] = l; }
            }
            acc += n;
        }
    }
    for (int j = t; j < EN; j += blockDim.x) {
        float ex = (2.0f * (float)(j >> 1)) / (float)EN;
        g_freq[j] = 6.283185307179586f * expf(-ex * 9.210340371976184f);
    }
}

// ---------------- trig table (d-independent) ----------------
__global__ void trig_kernel() {
    int idx = blockIdx.x * blockDim.x + threadIdx.x;
    if (idx >= NTAB * EN) return;
    int j = idx & (EN - 1);
    int i = idx >> 8;
    float t = (float)i * (1.0f / (float)(NTAB - 1));
    float a = t * g_freq[j];
    g_trig[idx] = (j & 1) ? __cosf(a) : __sinf(a);
}

// ---------------- trans ----------------
__global__ void trans_kernel(const float* __restrict__ rp, const float* __restrict__ ptm) {
    int idx = blockIdx.x * blockDim.x + threadIdx.x;
    if (idx >= TOTC * QN) return;
    int c = idx / QN;
    int b = g_cav_batch[c], l = g_cav_local[c];
    float r0 = rp[idx*3+0] * 281.6f - 140.8f;
    float r1 = rp[idx*3+1] *  80.0f -  40.0f;
    float r2 = rp[idx*3+2] *   4.0f -   3.0f;
    const float* T = ptm + (size_t)((b * LMAXC + l) * LMAXC) * 16;
    #pragma unroll
    for (int i = 0; i < 3; i++) {
        float z = fmaf(T[i*4+0], r0, fmaf(T[i*4+1], r1, fmaf(T[i*4+2], r2, T[i*4+3])));
        g_trans[idx*3+i] = 1.0f / (1.0f + expf(-z));
    }
}

// ---------------- fused weight precompute: wcat/bkp + wowq/bqo ----------------
__global__ void wpre_kernel(const float* __restrict__ in_w, const float* __restrict__ in_b,
                            const float* __restrict__ w2,   const float* __restrict__ b2,
                            const float* __restrict__ ow,   const float* __restrict__ ob) {
    __shared__ float sWk[EN];
    __shared__ float sWq[EN];
    __shared__ float red[EN];
    int n = blockIdx.x, j = threadIdx.x;
    sWk[j] = in_w[(size_t)(EN + n)*EN + j];
    sWq[j] = in_w[(size_t)n*EN + j];
    __syncthreads();
    // wcat = [Wk | Wk@W2]
    {
        float a0=0.f,a1=0.f,a2=0.f,a3=0.f;
        #pragma unroll 4
        for (int m = 0; m < EN; m += 4) {
            a0 = fmaf(sWk[m+0], w2[(size_t)(m+0)*EN + j], a0);
            a1 = fmaf(sWk[m+1], w2[(size_t)(m+1)*EN + j], a1);
            a2 = fmaf(sWk[m+2], w2[(size_t)(m+2)*EN + j], a2);
            a3 = fmaf(sWk[m+3], w2[(size_t)(m+3)*EN + j], a3);
        }
        g_wcat[(size_t)n*512 + j]      = sWk[j];
        g_wcat[(size_t)n*512 + EN + j] = (a0+a1)+(a2+a3);
    }
    // wowq = Wq @ Wo
    {
        float a0=0.f,a1=0.f,a2=0.f,a3=0.f;
        #pragma unroll 4
        for (int m = 0; m < EN; m += 4) {
            a0 = fmaf(sWq[m+0], ow[(size_t)(m+0)*EN + j], a0);
            a1 = fmaf(sWq[m+1], ow[(size_t)(m+1)*EN + j], a1);
            a2 = fmaf(sWq[m+2], ow[(size_t)(m+2)*EN + j], a2);
            a3 = fmaf(sWq[m+3], ow[(size_t)(m+3)*EN + j], a3);
        }
        g_wowq[(size_t)n*EN + j] = (a0+a1)+(a2+a3);
    }
    // bkp = bk + Wk@b2
    red[j] = sWk[j] * b2[j];
    __syncthreads();
    for (int s = 128; s > 0; s >>= 1) {
        if (j < s) red[j] += red[j + s];
        __syncthreads();
    }
    if (j == 0) g_bkp[n] = in_b[EN + n] + red[0];
    __syncthreads();
    // bqo = Wq@bo
    red[j] = sWq[j] * ob[j];
    __syncthreads();
    for (int s = 128; s > 0; s >>= 1) {
        if (j < s) red[j] += red[j + s];
        __syncthreads();
    }
    if (j == 0) g_bqo[n] = red[0];
}

// ---------------- hidden = relu(b1 + sum_d lerp(table_d, t_d)) ----------------
__global__ void bev_lookup(const float* __restrict__ b1) {
    int idx = blockIdx.x * blockDim.x + threadIdx.x;
    if (idx >= TOTC*QN*(EN/4)) return;
    int n4  = idx & 63;
    int row = idx >> 6;
    int cav = row >> 11;
    if (g_cav_local[cav] == 0 || g_batch_n[g_cav_batch[cav]] <= 1) return;
    float4 acc = *(const float4*)(b1 + n4*4);
    #pragma unroll
    for (int d = 0; d < 3; d++) {
        float tv = g_trans[(size_t)row*3 + d];
        float u  = tv * (float)(NTAB - 1);
        int i0 = (int)u;
        if (i0 < 0) i0 = 0;
        if (i0 > NTAB-2) i0 = NTAB-2;
        float w = u - (float)i0;
        const float* r = g_table + ((size_t)(d*NTAB + i0))*EN + n4*4;
        float4 a = *(const float4*)r;
        float4 b = *(const float4*)(r + EN);
        acc.x = fmaf(w, b.x - a.x, acc.x + a.x);
        acc.y = fmaf(w, b.y - a.y, acc.y + a.y);
        acc.z = fmaf(w, b.z - a.z, acc.z + a.z);
        acc.w = fmaf(w, b.w - a.w, acc.w + a.w);
    }
    float4 o = make_float4(fmaxf(acc.x,0.f), fmaxf(acc.y,0.f), fmaxf(acc.z,0.f), fmaxf(acc.w,0.f));
    *(float4*)(g_hidden + (size_t)row*EN + n4*4) = o;
}

// ================= bf16-split tensor-core GEMM =================
__device__ __forceinline__ uint32_t s2u(const void* p) {
    uint32_t a;
    asm("{ .reg .u64 t; cvta.to.shared.u64 t, %1; cvt.u32.u64 %0, t; }" : "=r"(a) : "l"(p));
    return a;
}
__device__ __forceinline__ void ldm4(uint32_t* f, uint32_t addr) {
    asm volatile("ldmatrix.sync.aligned.m8n8.x4.shared.b16 {%0,%1,%2,%3}, [%4];"
        : "=r"(f[0]),"=r"(f[1]),"=r"(f[2]),"=r"(f[3]) : "r"(addr));
}
__device__ __forceinline__ void mmabf(float* c, const uint32_t* a, const uint32_t* b) {
    asm volatile("mma.sync.aligned.m16n8k16.row.col.f32.bf16.bf16.f32 "
        "{%0,%1,%2,%3}, {%4,%5,%6,%7}, {%8,%9}, {%0,%1,%2,%3};"
        : "+f"(c[0]),"+f"(c[1]),"+f"(c[2]),"+f"(c[3])
        : "r"(a[0]),"r"(a[1]),"r"(a[2]),"r"(a[3]), "r"(b[0]),"r"(b[1]));
}
__device__ __forceinline__ uint32_t pkbf(float a, float b) {
    __nv_bfloat162 t = __floats2bfloat162_rn(a, b);
    return *(uint32_t*)&t;
}

#define TSTR 24
#define TSZ  (128*TSTR)

// MODE 1: kp   = [x|hidden] @ wcat^T + bkp               (K=512, neighbor cavs)
// MODE 2: vp   = x @ Wv^T + bv                           (neighbor cavs)
// MODE 3: qpA  = x_ego @ Wq^T + bq                       (multi batches)
// MODE 6: table = trig @ W1_d^T                          (all blocks, bn -> d/nloc)
// MODE 7: qpB  = nm*(ctx@wowq^T + bqo) + nm*(qpA-bq)+bq  (multi batches)
// MODE 8: out_ego = ctx@Wo^T + nm2*x_ego + (nm2+nm)*bo   (final, writes OUT)
template<int MODE, int KT>
__global__ __launch_bounds__(256) void mma_gemm(const float* __restrict__ W,
                                                const float* __restrict__ bias,
                                                const float* __restrict__ X,
                                                float* __restrict__ OUT) {
    __shared__ __align__(16) __nv_bfloat16 sm[2*4*TSZ];

    const int bm = blockIdx.x, bn = blockIdx.y;
    int cav = 0;
    float scale = 1.0f;
    int bofs = 0;
    if (MODE == 1 || MODE == 2) {
        cav = bm >> 4;
        if (g_cav_local[cav] == 0 || g_batch_n[g_cav_batch[cav]] <= 1) return;
    } else if (MODE == 3 || MODE == 7 || MODE == 8) {
        int batch = bm >> 4;
        int n = g_batch_n[batch];
        if (n <= 1) return;
        scale = (float)(n - 1);
        bofs = g_batch_off[batch];
    }
    const int t    = threadIdx.x;
    const int lane = t & 31, wid = t >> 5;
    const int wm   = wid & 3, wn = wid >> 2;
    const int m0   = bm * 128, n0 = bn * 128;
    const int lrow = t >> 1;
    const int lk   = (t & 1) * 8;

    const int aoff  = (wm*32 + (lane & 7) + ((lane >> 3) & 1) * 8) * TSTR + (lane >> 4) * 8;
    const int woff2 = (wn*64 + (lane & 7) + (lane >> 4) * 8) * TSTR + ((lane >> 3) & 1) * 8;

    const uint32_t smb = s2u(sm);

    float4 va0, va1, vw0, vw1;
    auto ld = [&](int kt) {
        const int k0 = kt * 16 + lk;
        const int arow = m0 + lrow;
        const float* s;
        if (MODE == 1) {
            if (k0 < 256) { int q = arow & (QN-1); s = X + (size_t)q*(TOTC*EN) + cav*EN + k0; }
            else            s = g_hidden + (size_t)arow*EN + (k0 - 256);
        } else if (MODE == 2) {
            int q = arow & (QN-1); s = X + (size_t)q*(TOTC*EN) + cav*EN + k0;
        } else if (MODE == 3) {
            int q = arow & (QN-1); s = X + (size_t)q*(TOTC*EN) + bofs*EN + k0;
        } else if (MODE == 6) {
            s = g_trig + (size_t)arow*EN + k0;
        } else {
            s = g_ctx + (size_t)arow*EN + k0;
        }
        va0 = *(const float4*)s;  va1 = *(const float4*)(s + 4);
        const float* ws;
        if (MODE == 1)      ws = g_wcat + (size_t)(n0 + lrow)*512 + k0;
        else if (MODE == 6) {
            int d = bn >> 1, nloc = (bn & 1) * 128;
            ws = W + (size_t)(nloc + lrow)*768 + d*256 + k0;
        }
        else if (MODE == 7) ws = g_wowq + (size_t)(n0 + lrow)*EN + k0;
        else                ws = W + (size_t)(n0 + lrow)*EN + k0;
        vw0 = *(const float4*)ws; vw1 = *(const float4*)(ws + 4);
    };
    auto st = [&](int stage) {
        float a[8] = {va0.x,va0.y,va0.z,va0.w, va1.x,va1.y,va1.z,va1.w};
        float w[8] = {vw0.x,vw0.y,vw0.z,vw0.w, vw1.x,vw1.y,vw1.z,vw1.w};
        float ah[8], wh[8];
        uint32_t hi[4], lo[4];
        #pragma unroll
        for (int i = 0; i < 8; i++) ah[i] = __bfloat162float(__float2bfloat16_rn(a[i]));
        #pragma unroll
        for (int i = 0; i < 4; i++) {
            hi[i] = pkbf(ah[2*i], ah[2*i+1]);
            lo[i] = pkbf(a[2*i] - ah[2*i], a[2*i+1] - ah[2*i+1]);
        }
        const int eo = lrow * TSTR + lk;
        *(uint4*)&sm[(stage*4+0)*TSZ + eo] = make_uint4(hi[0],hi[1],hi[2],hi[3]);
        *(uint4*)&sm[(stage*4+1)*TSZ + eo] = make_uint4(lo[0],lo[1],lo[2],lo[3]);
        #pragma unroll
        for (int i = 0; i < 8; i++) wh[i] = __bfloat162float(__float2bfloat16_rn(w[i]));
        #pragma unroll
        for (int i = 0; i < 4; i++) {
            hi[i] = pkbf(wh[2*i], wh[2*i+1]);
            lo[i] = pkbf(w[2*i] - wh[2*i], w[2*i+1] - wh[2*i+1]);
        }
        *(uint4*)&sm[(stage*4+2)*TSZ + eo] = make_uint4(hi[0],hi[1],hi[2],hi[3]);
        *(uint4*)&sm[(stage*4+3)*TSZ + eo] = make_uint4(lo[0],lo[1],lo[2],lo[3]);
    };

    float acc[2][8][4] = {};

    ld(0); st(0);
    __syncthreads();
    for (int kt = 0; kt < KT; kt++) {
        if (kt + 1 < KT) ld(kt + 1);
        const int stage = kt & 1;
        const uint32_t bA = smb + (stage*4+0)*TSZ*2 + aoff*2;
        const uint32_t bAl= smb + (stage*4+1)*TSZ*2 + aoff*2;
        const uint32_t bW = smb + (stage*4+2)*TSZ*2 + woff2*2;
        const uint32_t bWl= smb + (stage*4+3)*TSZ*2 + woff2*2;

        uint32_t Ahi[2][4], Alo[2][4];
        #pragma unroll
        for (int ms = 0; ms < 2; ms++) {
            ldm4(Ahi[ms], bA  + ms*16*TSTR*2);
            ldm4(Alo[ms], bAl + ms*16*TSTR*2);
        }
        #pragma unroll
        for (int g = 0; g < 2; g++) {
            uint32_t Bhi[2][4], Blo[2][4];
            #pragma unroll
            for (int j = 0; j < 2; j++) {
                ldm4(Bhi[j], bW  + (2*g+j)*16*TSTR*2);
                ldm4(Blo[j], bWl + (2*g+j)*16*TSTR*2);
            }
            #pragma unroll
            for (int j = 0; j < 2; j++)
                #pragma unroll
                for (int ms = 0; ms < 2; ms++) {
                    mmabf(acc[ms][2*(2*g+j)],   Ahi[ms], Bhi[j]);
                    mmabf(acc[ms][2*(2*g+j)+1], Ahi[ms], Bhi[j]+2);
                }
            #pragma unroll
            for (int j = 0; j < 2; j++)
                #pragma unroll
                for (int ms = 0; ms < 2; ms++) {
                    mmabf(acc[ms][2*(2*g+j)],   Alo[ms], Bhi[j]);
                    mmabf(acc[ms][2*(2*g+j)+1], Alo[ms], Bhi[j]+2);
                }
            #pragma unroll
            for (int j = 0; j < 2; j++)
                #pragma unroll
                for (int ms = 0; ms < 2; ms++) {
                    mmabf(acc[ms][2*(2*g+j)],   Ahi[ms], Blo[j]);
                    mmabf(acc[ms][2*(2*g+j)+1], Ahi[ms], Blo[j]+2);
                }
        }
        if (kt + 1 < KT) st(stage ^ 1);
        __syncthreads();
    }

    // epilogue
    #pragma unroll
    for (int ms = 0; ms < 2; ms++) {
        const int row = m0 + wm*32 + ms*16 + (lane >> 2);
        #pragma unroll
        for (int ns = 0; ns < 8; ns++) {
            const int nlocal = wn*64 + ns*8 + (lane & 3)*2;   // 0..126 within tile
            const int col = n0 + nlocal;
            #pragma unroll
            for (int h = 0; h < 2; h++) {
                const int r = row + h*8;
                float v0 = acc[ms][ns][2*h];
                float v1 = acc[ms][ns][2*h+1];
                if (MODE == 1) {
                    float* dst = g_kp + (size_t)r*EN + col;
                    *(float2*)dst = make_float2(v0 + g_bkp[col], v1 + g_bkp[col+1]);
                } else if (MODE == 2) {
                    float* dst = g_vp + (size_t)r*EN + col;
                    *(float2*)dst = make_float2(v0 + bias[col], v1 + bias[col+1]);
                } else if (MODE == 3) {
                    float* dst = g_qpA + (size_t)r*EN + col;
                    *(float2*)dst = make_float2(v0 + bias[col], v1 + bias[col+1]);
                } else if (MODE == 6) {
                    int d = bn >> 1, nloc = (bn & 1) * 128;
                    float* dst = g_table + ((size_t)(d*NTAB + r))*EN + nloc + nlocal;
                    *(float2*)dst = make_float2(v0, v1);
                } else if (MODE == 7) {
                    // qpB = nm*(acc + bqo) + nm*(qpA - bq) + bq
                    const size_t o = (size_t)r*EN + col;
                    float q10 = g_qpA[o], q11 = g_qpA[o+1];
                    float bq0 = bias[col], bq1 = bias[col+1];
                    float o0 = scale*(v0 + g_bqo[col])   + scale*(q10 - bq0) + bq0;
                    float o1 = scale*(v1 + g_bqo[col+1]) + scale*(q11 - bq1) + bq1;
                    *(float2*)(g_qpB + o) = make_float2(o0, o1);
                } else {
                    // MODE 8: out_ego = acc + nm2*x_ego + (nm2+nm)*bo
                    const float nm2 = scale * scale;
                    int q = r & (QN - 1);
                    const float* xr = X + (size_t)q*(TOTC*EN) + bofs*EN + col;
                    float o0 = v0 + nm2*xr[0] + (nm2 + scale)*bias[col];
                    float o1 = v1 + nm2*xr[1] + (nm2 + scale)*bias[col+1];
                    float* dst = OUT + ((size_t)q*TOTC + bofs)*EN + col;
                    *(float2*)dst = make_float2(o0, o1);
                }
            }
        }
    }
}

// ---------------- degenerate attention ----------------
// it==0: ctx = attn(qpA)           -> g_ctx
// it==1: g_ctx = nm^2*g_ctx + nm*attn(qpB)
__global__ void attn_kernel(int it) {
    int w = (blockIdx.x * blockDim.x + threadIdx.x) >> 5;
    int lane = threadIdx.x & 31;
    if (w >= NB * QN * NH) return;
    int h  = w & 7;
    int bq = w >> 3;
    int b  = bq >> 11;
    int q  = bq & (QN - 1);
    int n  = g_batch_n[b];
    if (n <= 1) return;
    int nm  = n - 1;
    int off = g_batch_off[b];
    int col = h * 32 + lane;

    const float* qp = (it == 0) ? g_qpA : g_qpB;
    float qv = qp[(size_t)bq*EN + col];
    float sc[LMAXC - 1];
    for (int m = 0; m < nm; m++) {
        int c = off + 1 + m;
        float p = qv * g_kp[(size_t)(c*QN + q)*EN + col];
        #pragma unroll
        for (int o = 16; o; o >>= 1) p += __shfl_xor_sync(0xffffffffu, p, o);
        sc[m] = p * 0.17677669529663687f;
    }
    float mx = -1e30f;
    for (int m = 0; m < nm; m++) mx = fmaxf(mx, sc[m]);
    float s = 0.0f, wt[LMAXC - 1];
    for (int m = 0; m < nm; m++) { wt[m] = __expf(sc[m] - mx); s += wt[m]; }
    float inv = 1.0f / s;
    float ctx = 0.0f;
    for (int m = 0; m < nm; m++) {
        int c = off + 1 + m;
        ctx = fmaf(wt[m] * inv, g_vp[(size_t)(c*QN + q)*EN + col], ctx);
    }
    const size_t o = (size_t)bq*EN + col;
    if (it == 0) {
        g_ctx[o] = ctx;
    } else {
        float fnm = (float)nm;
        g_ctx[o] = fnm*fnm*g_ctx[o] + fnm*ctx;
    }
}

// ---------------- launch (fork-join multi-stream) ----------------
extern "C" void kernel_launch(void* const* d_in, const int* in_sizes, int n_in,
                              void* d_out, int out_size) {
    const float*     x    = (const float*)d_in[0];
    const float*     rp   = (const float*)d_in[1];
    const float*     ptm  = (const float*)d_in[2];
    const long long* rl   = (const long long*)d_in[3];
    const float*     in_w = (const float*)d_in[4];
    const float*     in_b = (const float*)d_in[5];
    const float*     ow   = (const float*)d_in[6];
    const float*     ob   = (const float*)d_in[7];
    const float*     w1   = (const float*)d_in[8];
    const float*     b1   = (const float*)d_in[9];
    const float*     w2   = (const float*)d_in[10];
    const float*     b2   = (const float*)d_in[11];
    float* out = (float*)d_out;

    static cudaStream_t sB = nullptr, sC = nullptr, sD = nullptr;
    static cudaEvent_t  ev0 = nullptr, evB = nullptr, evC = nullptr, evX = nullptr;
    if (sB == nullptr) {
        cudaStreamCreateWithFlags(&sB, cudaStreamNonBlocking);
        cudaStreamCreateWithFlags(&sC, cudaStreamNonBlocking);
        cudaStreamCreateWithFlags(&sD, cudaStreamNonBlocking);
        cudaEventCreateWithFlags(&ev0, cudaEventDisableTiming);
        cudaEventCreateWithFlags(&evB, cudaEventDisableTiming);
        cudaEventCreateWithFlags(&evC, cudaEventDisableTiming);
        cudaEventCreateWithFlags(&evX, cudaEventDisableTiming);
    }

    dim3 gcav(TOTC*QN/128, 2);      // 640 x 2
    dim3 gego(NB*QN/128, 2);        // 128 x 2
    dim3 gtab(NTAB/128, 6);         // 16 x 6

    // main: setup then fork everything off ev0
    setup_kernel<<<1, 256>>>(rl);
    cudaEventRecord(ev0, 0);

    // stream D: bulk copy x -> out
    cudaStreamWaitEvent(sD, ev0, 0);
    cudaMemcpyAsync(out, x, (size_t)QN*TOTC*EN*sizeof(float),
                    cudaMemcpyDeviceToDevice, sD);
    cudaEventRecord(evX, sD);

    // stream B: vp + qp1 (both read x only + setup maps)
    cudaStreamWaitEvent(sB, ev0, 0);
    mma_gemm<2,16><<<gcav, 256, 0, sB>>>(in_w + 512*EN, in_b + 512, x, out);   // vp
    mma_gemm<3,16><<<gego, 256, 0, sB>>>(in_w, in_b, x, out);                  // qpA
    cudaEventRecord(evB, sB);

    // stream C: fused weight precompute
    cudaStreamWaitEvent(sC, ev0, 0);
    wpre_kernel<<<EN, EN, 0, sC>>>(in_w, in_b, w2, b2, ow, ob);
    cudaEventRecord(evC, sC);

    // main: trig -> tableGEMM -> trans -> bev -> (join wkk) kp
    trig_kernel<<<(NTAB*EN + 255)/256, 256>>>();
    mma_gemm<6,16><<<gtab, 256>>>(w1, nullptr, nullptr, nullptr);              // table
    trans_kernel<<<(TOTC*QN + 255)/256, 256>>>(rp, ptm);
    bev_lookup<<<(TOTC*QN*(EN/4) + 255)/256, 256>>>(b1);
    cudaStreamWaitEvent(0, evC, 0);
    mma_gemm<1,32><<<gcav, 256>>>(nullptr, nullptr, x, out);                   // kp (K=512)

    // join stream B, then the shortened attention chain
    cudaStreamWaitEvent(0, evB, 0);
    attn_kernel<<<NB*QN*NH*32/256, 256>>>(0);                                  // ctx1
    mma_gemm<7,16><<<gego, 256>>>(nullptr, in_b, x, out);                      // qpB from ctx1
    attn_kernel<<<NB*QN*NH*32/256, 256>>>(1);                                  // cmix
    cudaStreamWaitEvent(0, evX, 0);
    mma_gemm<8,16><<<gego, 256>>>(ow, ob, x, out);                             // final -> out
}

// round 11
// speedup vs baseline: 1.2235x; 1.0045x over previous
#include <cuda_runtime.h>
#include <cuda_bf16.h>
#include <cstdint>

#define QN    2048
#define EN    256
#define TOTC  40
#define NB    8
#define LMAXC 5
#define NH    8
#define NTAB  2048

// ---------------- scratch ----------------
__device__ float g_trans [TOTC*QN*3];
__device__ float g_hidden[TOTC*QN*EN];
__device__ float g_kp    [TOTC*QN*EN];
__device__ float g_vp    [TOTC*QN*EN];
__device__ float g_qpA   [NB*QN*EN];
__device__ float g_qpB   [NB*QN*EN];
__device__ float g_ctx   [NB*QN*EN];
__device__ float g_table [3*NTAB*EN];
__device__ float g_trig  [NTAB*EN];
__device__ float g_wcat  [EN*512];
__device__ float g_bkp   [EN];
__device__ float g_wowq  [EN*EN];
__device__ float g_bqo   [EN];
__device__ float g_freq  [EN];
__device__ int   g_cav_batch[TOTC];
__device__ int   g_cav_local[TOTC];
__device__ int   g_batch_n  [NB];
__device__ int   g_batch_off[NB];

// ---------------- setup ----------------
__global__ void setup_kernel(const long long* __restrict__ rl64) {
    int t = threadIdx.x;
    if (t == 0) {
        bool ok64 = true;
        for (int b = 0; b < NB; b++) {
            long long v = rl64[b];
            if (v < 1 || v > LMAXC) ok64 = false;
        }
        const int* rl32 = (const int*)rl64;
        int acc = 0;
        for (int c = 0; c < TOTC; c++) { g_cav_batch[c] = 0; g_cav_local[c] = 0; }
        for (int b = 0; b < NB; b++) {
            int n = ok64 ? (int)rl64[b] : rl32[b];
            if (n < 1) n = 1;
            if (n > LMAXC) n = LMAXC;
            g_batch_n[b] = n; g_batch_off[b] = acc;
            for (int l = 0; l < n; l++) {
                int c = acc + l;
                if (c < TOTC) { g_cav_batch[c] = b; g_cav_local[c] = l; }
            }
            acc += n;
        }
    }
    for (int j = t; j < EN; j += blockDim.x) {
        float ex = (2.0f * (float)(j >> 1)) / (float)EN;
        g_freq[j] = 6.283185307179586f * expf(-ex * 9.210340371976184f);
    }
}

// ---------------- trig table (d-independent) ----------------
__global__ void trig_kernel() {
    int idx = blockIdx.x * blockDim.x + threadIdx.x;
    if (idx >= NTAB * EN) return;
    int j = idx & (EN - 1);
    int i = idx >> 8;
    float t = (float)i * (1.0f / (float)(NTAB - 1));
    float a = t * g_freq[j];
    g_trig[idx] = (j & 1) ? __cosf(a) : __sinf(a);
}

// ---------------- trans ----------------
__global__ void trans_kernel(const float* __restrict__ rp, const float* __restrict__ ptm) {
    int idx = blockIdx.x * blockDim.x + threadIdx.x;
    if (idx >= TOTC * QN) return;
    int c = idx / QN;
    int b = g_cav_batch[c], l = g_cav_local[c];
    float r0 = rp[idx*3+0] * 281.6f - 140.8f;
    float r1 = rp[idx*3+1] *  80.0f -  40.0f;
    float r2 = rp[idx*3+2] *   4.0f -   3.0f;
    const float* T = ptm + (size_t)((b * LMAXC + l) * LMAXC) * 16;
    #pragma unroll
    for (int i = 0; i < 3; i++) {
        float z = fmaf(T[i*4+0], r0, fmaf(T[i*4+1], r1, fmaf(T[i*4+2], r2, T[i*4+3])));
        g_trans[idx*3+i] = 1.0f / (1.0f + expf(-z));
    }
}

// ---------------- fused weight precompute: wcat/bkp + wowq/bqo ----------------
__global__ void wpre_kernel(const float* __restrict__ in_w, const float* __restrict__ in_b,
                            const float* __restrict__ w2,   const float* __restrict__ b2,
                            const float* __restrict__ ow,   const float* __restrict__ ob) {
    __shared__ float sWk[EN];
    __shared__ float sWq[EN];
    __shared__ float red[EN];
    int n = blockIdx.x, j = threadIdx.x;
    sWk[j] = in_w[(size_t)(EN + n)*EN + j];
    sWq[j] = in_w[(size_t)n*EN + j];
    __syncthreads();
    {
        float a0=0.f,a1=0.f,a2=0.f,a3=0.f;
        #pragma unroll 4
        for (int m = 0; m < EN; m += 4) {
            a0 = fmaf(sWk[m+0], w2[(size_t)(m+0)*EN + j], a0);
            a1 = fmaf(sWk[m+1], w2[(size_t)(m+1)*EN + j], a1);
            a2 = fmaf(sWk[m+2], w2[(size_t)(m+2)*EN + j], a2);
            a3 = fmaf(sWk[m+3], w2[(size_t)(m+3)*EN + j], a3);
        }
        g_wcat[(size_t)n*512 + j]      = sWk[j];
        g_wcat[(size_t)n*512 + EN + j] = (a0+a1)+(a2+a3);
    }
    {
        float a0=0.f,a1=0.f,a2=0.f,a3=0.f;
        #pragma unroll 4
        for (int m = 0; m < EN; m += 4) {
            a0 = fmaf(sWq[m+0], ow[(size_t)(m+0)*EN + j], a0);
            a1 = fmaf(sWq[m+1], ow[(size_t)(m+1)*EN + j], a1);
            a2 = fmaf(sWq[m+2], ow[(size_t)(m+2)*EN + j], a2);
            a3 = fmaf(sWq[m+3], ow[(size_t)(m+3)*EN + j], a3);
        }
        g_wowq[(size_t)n*EN + j] = (a0+a1)+(a2+a3);
    }
    red[j] = sWk[j] * b2[j];
    __syncthreads();
    for (int s = 128; s > 0; s >>= 1) {
        if (j < s) red[j] += red[j + s];
        __syncthreads();
    }
    if (j == 0) g_bkp[n] = in_b[EN + n] + red[0];
    __syncthreads();
    red[j] = sWq[j] * ob[j];
    __syncthreads();
    for (int s = 128; s > 0; s >>= 1) {
        if (j < s) red[j] += red[j + s];
        __syncthreads();
    }
    if (j == 0) g_bqo[n] = red[0];
}

// ---------------- hidden = relu(b1 + sum_d lerp(table_d, t_d)) ----------------
__global__ void bev_lookup(const float* __restrict__ b1) {
    int idx = blockIdx.x * blockDim.x + threadIdx.x;
    if (idx >= TOTC*QN*(EN/4)) return;
    int n4  = idx & 63;
    int row = idx >> 6;
    int cav = row >> 11;
    if (g_cav_local[cav] == 0 || g_batch_n[g_cav_batch[cav]] <= 1) return;
    float4 acc = *(const float4*)(b1 + n4*4);
    #pragma unroll
    for (int d = 0; d < 3; d++) {
        float tv = g_trans[(size_t)row*3 + d];
        float u  = tv * (float)(NTAB - 1);
        int i0 = (int)u;
        if (i0 < 0) i0 = 0;
        if (i0 > NTAB-2) i0 = NTAB-2;
        float w = u - (float)i0;
        const float* r = g_table + ((size_t)(d*NTAB + i0))*EN + n4*4;
        float4 a = *(const float4*)r;
        float4 b = *(const float4*)(r + EN);
        acc.x = fmaf(w, b.x - a.x, acc.x + a.x);
        acc.y = fmaf(w, b.y - a.y, acc.y + a.y);
        acc.z = fmaf(w, b.z - a.z, acc.z + a.z);
        acc.w = fmaf(w, b.w - a.w, acc.w + a.w);
    }
    float4 o = make_float4(fmaxf(acc.x,0.f), fmaxf(acc.y,0.f), fmaxf(acc.z,0.f), fmaxf(acc.w,0.f));
    *(float4*)(g_hidden + (size_t)row*EN + n4*4) = o;
}

// ================= bf16-split tensor-core GEMM (64x64 warp tiles) =================
__device__ __forceinline__ uint32_t s2u(const void* p) {
    uint32_t a;
    asm("{ .reg .u64 t; cvta.to.shared.u64 t, %1; cvt.u32.u64 %0, t; }" : "=r"(a) : "l"(p));
    return a;
}
__device__ __forceinline__ void ldm4(uint32_t* f, uint32_t addr) {
    asm volatile("ldmatrix.sync.aligned.m8n8.x4.shared.b16 {%0,%1,%2,%3}, [%4];"
        : "=r"(f[0]),"=r"(f[1]),"=r"(f[2]),"=r"(f[3]) : "r"(addr));
}
__device__ __forceinline__ void mmabf(float* c, const uint32_t* a, const uint32_t* b) {
    asm volatile("mma.sync.aligned.m16n8k16.row.col.f32.bf16.bf16.f32 "
        "{%0,%1,%2,%3}, {%4,%5,%6,%7}, {%8,%9}, {%0,%1,%2,%3};"
        : "+f"(c[0]),"+f"(c[1]),"+f"(c[2]),"+f"(c[3])
        : "r"(a[0]),"r"(a[1]),"r"(a[2]),"r"(a[3]), "r"(b[0]),"r"(b[1]));
}
__device__ __forceinline__ uint32_t pkbf(float a, float b) {
    __nv_bfloat162 t = __floats2bfloat162_rn(a, b);
    return *(uint32_t*)&t;
}

#define TSTR 24
#define TSZ  (128*TSTR)                    // halves per operand tile
#define GSMEM (2*4*TSZ*2)                  // 2 stages x 4 operands x TSZ halves x 2B = 49152

// MODE 1: kp   = [x|hidden] @ wcat^T + bkp               (K=512, neighbor cavs)
// MODE 2: vp   = x @ Wv^T + bv                           (neighbor cavs)
// MODE 3: qpA  = x_ego @ Wq^T + bq                       (multi batches)
// MODE 6: table = trig @ W1_d^T                          (bn -> d/nloc)
// MODE 7: qpB  = nm*(ctx@wowq^T + bqo) + nm*(qpA-bq)+bq  (multi batches)
// MODE 8: out_ego = ctx@Wo^T + nm2*x_ego + (nm2+nm)*bo   (final, writes OUT)
template<int MODE, int KT>
__global__ __launch_bounds__(128, 2) void mma_gemm(const float* __restrict__ W,
                                                   const float* __restrict__ bias,
                                                   const float* __restrict__ X,
                                                   float* __restrict__ OUT) {
    extern __shared__ __align__(16) __nv_bfloat16 sm[];

    const int bm = blockIdx.x, bn = blockIdx.y;
    int cav = 0;
    float scale = 1.0f;
    int bofs = 0;
    if (MODE == 1 || MODE == 2) {
        cav = bm >> 4;
        if (g_cav_local[cav] == 0 || g_batch_n[g_cav_batch[cav]] <= 1) return;
    } else if (MODE == 3 || MODE == 7 || MODE == 8) {
        int batch = bm >> 4;
        int n = g_batch_n[batch];
        if (n <= 1) return;
        scale = (float)(n - 1);
        bofs = g_batch_off[batch];
    }
    const int t    = threadIdx.x;
    const int lane = t & 31, wid = t >> 5;          // 4 warps
    const int wm   = wid & 1, wn = wid >> 1;        // 2x2 of 64x64 tiles
    const int m0   = bm * 128, n0 = bn * 128;
    const int lrow4 = t >> 2;                       // 0..31
    const int lf4   = t & 3;                        // which float4 of the 16-k chunk

    const int aoff = (wm*64 + (lane & 7) + ((lane >> 3) & 1) * 8) * TSTR + (lane >> 4) * 8;
    const int woff = (wn*64 + (lane & 7) + (lane >> 4) * 8) * TSTR + ((lane >> 3) & 1) * 8;

    const uint32_t smb = s2u(sm);

    float4 va[4], vw[4];
    auto ld = [&](int kt) {
        const int k0 = kt * 16 + lf4 * 4;
        #pragma unroll
        for (int rr = 0; rr < 4; rr++) {
            const int row = lrow4 + rr * 32;
            const int arow = m0 + row;
            const float* s;
            if (MODE == 1) {
                if (k0 < 256) { int q = arow & (QN-1); s = X + (size_t)q*(TOTC*EN) + cav*EN + k0; }
                else            s = g_hidden + (size_t)arow*EN + (k0 - 256);
            } else if (MODE == 2) {
                int q = arow & (QN-1); s = X + (size_t)q*(TOTC*EN) + cav*EN + k0;
            } else if (MODE == 3) {
                int q = arow & (QN-1); s = X + (size_t)q*(TOTC*EN) + bofs*EN + k0;
            } else if (MODE == 6) {
                s = g_trig + (size_t)arow*EN + k0;
            } else {
                s = g_ctx + (size_t)arow*EN + k0;
            }
            va[rr] = *(const float4*)s;
            const float* ws;
            if (MODE == 1)      ws = g_wcat + (size_t)(n0 + row)*512 + k0;
            else if (MODE == 6) {
                int d = bn >> 1, nloc = (bn & 1) * 128;
                ws = W + (size_t)(nloc + row)*768 + d*256 + k0;
            }
            else if (MODE == 7) ws = g_wowq + (size_t)(n0 + row)*EN + k0;
            else                ws = W + (size_t)(n0 + row)*EN + k0;
            vw[rr] = *(const float4*)ws;
        }
    };
    auto st = [&](int stage) {
        #pragma unroll
        for (int rr = 0; rr < 4; rr++) {
            const int eo = (lrow4 + rr*32) * TSTR + lf4 * 4;
            float a[4] = {va[rr].x, va[rr].y, va[rr].z, va[rr].w};
            float w[4] = {vw[rr].x, vw[rr].y, vw[rr].z, vw[rr].w};
            float ah[4], wh[4];
            #pragma unroll
            for (int i = 0; i < 4; i++) ah[i] = __bfloat162float(__float2bfloat16_rn(a[i]));
            #pragma unroll
            for (int i = 0; i < 4; i++) wh[i] = __bfloat162float(__float2bfloat16_rn(w[i]));
            uint2 ahv = make_uint2(pkbf(ah[0], ah[1]), pkbf(ah[2], ah[3]));
            uint2 alv = make_uint2(pkbf(a[0]-ah[0], a[1]-ah[1]), pkbf(a[2]-ah[2], a[3]-ah[3]));
            uint2 whv = make_uint2(pkbf(wh[0], wh[1]), pkbf(wh[2], wh[3]));
            uint2 wlv = make_uint2(pkbf(w[0]-wh[0], w[1]-wh[1]), pkbf(w[2]-wh[2], w[3]-wh[3]));
            *(uint2*)&sm[(stage*4+0)*TSZ + eo] = ahv;
            *(uint2*)&sm[(stage*4+1)*TSZ + eo] = alv;
            *(uint2*)&sm[(stage*4+2)*TSZ + eo] = whv;
            *(uint2*)&sm[(stage*4+3)*TSZ + eo] = wlv;
        }
    };

    float acc[4][8][4] = {};

    ld(0); st(0);
    __syncthreads();
    for (int kt = 0; kt < KT; kt++) {
        if (kt + 1 < KT) ld(kt + 1);
        const int stage = kt & 1;
        const uint32_t bA = smb + (stage*4+0)*TSZ*2 + aoff*2;
        const uint32_t bAl= smb + (stage*4+1)*TSZ*2 + aoff*2;
        const uint32_t bW = smb + (stage*4+2)*TSZ*2 + woff*2;
        const uint32_t bWl= smb + (stage*4+3)*TSZ*2 + woff*2;

        uint32_t Ahi[4][4], Alo[4][4];
        #pragma unroll
        for (int ms = 0; ms < 4; ms++) {
            ldm4(Ahi[ms], bA  + ms*16*TSTR*2);
            ldm4(Alo[ms], bAl + ms*16*TSTR*2);
        }
        #pragma unroll
        for (int np = 0; np < 4; np++) {
            uint32_t Bhi[4], Blo[4];
            ldm4(Bhi, bW  + np*16*TSTR*2);
            ldm4(Blo, bWl + np*16*TSTR*2);
            #pragma unroll
            for (int ms = 0; ms < 4; ms++) {
                mmabf(acc[ms][2*np],   Ahi[ms], Bhi);
                mmabf(acc[ms][2*np+1], Ahi[ms], Bhi+2);
                mmabf(acc[ms][2*np],   Alo[ms], Bhi);
                mmabf(acc[ms][2*np+1], Alo[ms], Bhi+2);
                mmabf(acc[ms][2*np],   Ahi[ms], Blo);
                mmabf(acc[ms][2*np+1], Ahi[ms], Blo+2);
            }
        }
        if (kt + 1 < KT) st(stage ^ 1);
        __syncthreads();
    }

    // epilogue
    #pragma unroll
    for (int ms = 0; ms < 4; ms++) {
        const int row = m0 + wm*64 + ms*16 + (lane >> 2);
        #pragma unroll
        for (int ns = 0; ns < 8; ns++) {
            const int nlocal = wn*64 + ns*8 + (lane & 3)*2;
            const int col = n0 + nlocal;
            #pragma unroll
            for (int h = 0; h < 2; h++) {
                const int r = row + h*8;
                float v0 = acc[ms][ns][2*h];
                float v1 = acc[ms][ns][2*h+1];
                if (MODE == 1) {
                    float* dst = g_kp + (size_t)r*EN + col;
                    *(float2*)dst = make_float2(v0 + g_bkp[col], v1 + g_bkp[col+1]);
                } else if (MODE == 2) {
                    float* dst = g_vp + (size_t)r*EN + col;
                    *(float2*)dst = make_float2(v0 + bias[col], v1 + bias[col+1]);
                } else if (MODE == 3) {
                    float* dst = g_qpA + (size_t)r*EN + col;
                    *(float2*)dst = make_float2(v0 + bias[col], v1 + bias[col+1]);
                } else if (MODE == 6) {
                    int d = bn >> 1, nloc = (bn & 1) * 128;
                    float* dst = g_table + ((size_t)(d*NTAB + r))*EN + nloc + nlocal;
                    *(float2*)dst = make_float2(v0, v1);
                } else if (MODE == 7) {
                    const size_t o = (size_t)r*EN + col;
                    float q10 = g_qpA[o], q11 = g_qpA[o+1];
                    float bq0 = bias[col], bq1 = bias[col+1];
                    float o0 = scale*(v0 + g_bqo[col])   + scale*(q10 - bq0) + bq0;
                    float o1 = scale*(v1 + g_bqo[col+1]) + scale*(q11 - bq1) + bq1;
                    *(float2*)(g_qpB + o) = make_float2(o0, o1);
                } else {
                    const float nm2 = scale * scale;
                    int q = r & (QN - 1);
                    const float* xr = X + (size_t)q*(TOTC*EN) + bofs*EN + col;
                    float o0 = v0 + nm2*xr[0] + (nm2 + scale)*bias[col];
                    float o1 = v1 + nm2*xr[1] + (nm2 + scale)*bias[col+1];
                    float* dst = OUT + ((size_t)q*TOTC + bofs)*EN + col;
                    *(float2*)dst = make_float2(o0, o1);
                }
            }
        }
    }
}

// ---------------- degenerate attention ----------------
__global__ void attn_kernel(int it) {
    int w = (blockIdx.x * blockDim.x + threadIdx.x) >> 5;
    int lane = threadIdx.x & 31;
    if (w >= NB * QN * NH) return;
    int h  = w & 7;
    int bq = w >> 3;
    int b  = bq >> 11;
    int q  = bq & (QN - 1);
    int n  = g_batch_n[b];
    if (n <= 1) return;
    int nm  = n - 1;
    int off = g_batch_off[b];
    int col = h * 32 + lane;

    const float* qp = (it == 0) ? g_qpA : g_qpB;
    float qv = qp[(size_t)bq*EN + col];
    float sc[LMAXC - 1];
    for (int m = 0; m < nm; m++) {
        int c = off + 1 + m;
        float p = qv * g_kp[(size_t)(c*QN + q)*EN + col];
        #pragma unroll
        for (int o = 16; o; o >>= 1) p += __shfl_xor_sync(0xffffffffu, p, o);
        sc[m] = p * 0.17677669529663687f;
    }
    float mx = -1e30f;
    for (int m = 0; m < nm; m++) mx = fmaxf(mx, sc[m]);
    float s = 0.0f, wt[LMAXC - 1];
    for (int m = 0; m < nm; m++) { wt[m] = __expf(sc[m] - mx); s += wt[m]; }
    float inv = 1.0f / s;
    float ctx = 0.0f;
    for (int m = 0; m < nm; m++) {
        int c = off + 1 + m;
        ctx = fmaf(wt[m] * inv, g_vp[(size_t)(c*QN + q)*EN + col], ctx);
    }
    const size_t o = (size_t)bq*EN + col;
    if (it == 0) {
        g_ctx[o] = ctx;
    } else {
        float fnm = (float)nm;
        g_ctx[o] = fnm*fnm*g_ctx[o] + fnm*ctx;
    }
}

// ---------------- launch (fork-join multi-stream) ----------------
extern "C" void kernel_launch(void* const* d_in, const int* in_sizes, int n_in,
                              void* d_out, int out_size) {
    const float*     x    = (const float*)d_in[0];
    const float*     rp   = (const float*)d_in[1];
    const float*     ptm  = (const float*)d_in[2];
    const long long* rl   = (const long long*)d_in[3];
    const float*     in_w = (const float*)d_in[4];
    const float*     in_b = (const float*)d_in[5];
    const float*     ow   = (const float*)d_in[6];
    const float*     ob   = (const float*)d_in[7];
    const float*     w1   = (const float*)d_in[8];
    const float*     b1   = (const float*)d_in[9];
    const float*     w2   = (const float*)d_in[10];
    const float*     b2   = (const float*)d_in[11];
    float* out = (float*)d_out;

    static cudaStream_t sB = nullptr, sC = nullptr, sD = nullptr;
    static cudaEvent_t  ev0 = nullptr, evB = nullptr, evC = nullptr, evX = nullptr;
    if (sB == nullptr) {
        cudaStreamCreateWithFlags(&sB, cudaStreamNonBlocking);
        cudaStreamCreateWithFlags(&sC, cudaStreamNonBlocking);
        cudaStreamCreateWithFlags(&sD, cudaStreamNonBlocking);
        cudaEventCreateWithFlags(&ev0, cudaEventDisableTiming);
        cudaEventCreateWithFlags(&evB, cudaEventDisableTiming);
        cudaEventCreateWithFlags(&evC, cudaEventDisableTiming);
        cudaEventCreateWithFlags(&evX, cudaEventDisableTiming);
        cudaFuncSetAttribute(mma_gemm<1,32>, cudaFuncAttributeMaxDynamicSharedMemorySize, GSMEM);
        cudaFuncSetAttribute(mma_gemm<2,16>, cudaFuncAttributeMaxDynamicSharedMemorySize, GSMEM);
        cudaFuncSetAttribute(mma_gemm<3,16>, cudaFuncAttributeMaxDynamicSharedMemorySize, GSMEM);
        cudaFuncSetAttribute(mma_gemm<6,16>, cudaFuncAttributeMaxDynamicSharedMemorySize, GSMEM);
        cudaFuncSetAttribute(mma_gemm<7,16>, cudaFuncAttributeMaxDynamicSharedMemorySize, GSMEM);
        cudaFuncSetAttribute(mma_gemm<8,16>, cudaFuncAttributeMaxDynamicSharedMemorySize, GSMEM);
    }

    dim3 gcav(TOTC*QN/128, 2);      // 640 x 2
    dim3 gego(NB*QN/128, 2);        // 128 x 2
    dim3 gtab(NTAB/128, 6);         // 16 x 6

    // main: setup then fork everything off ev0
    setup_kernel<<<1, 256>>>(rl);
    cudaEventRecord(ev0, 0);

    // stream D: bulk copy x -> out
    cudaStreamWaitEvent(sD, ev0, 0);
    cudaMemcpyAsync(out, x, (size_t)QN*TOTC*EN*sizeof(float),
                    cudaMemcpyDeviceToDevice, sD);
    cudaEventRecord(evX, sD);

    // stream B: vp + qpA (both read x only + setup maps)
    cudaStreamWaitEvent(sB, ev0, 0);
    mma_gemm<2,16><<<gcav, 128, GSMEM, sB>>>(in_w + 512*EN, in_b + 512, x, out);  // vp
    mma_gemm<3,16><<<gego, 128, GSMEM, sB>>>(in_w, in_b, x, out);                 // qpA
    cudaEventRecord(evB, sB);

    // stream C: fused weight precompute
    cudaStreamWaitEvent(sC, ev0, 0);
    wpre_kernel<<<EN, EN, 0, sC>>>(in_w, in_b, w2, b2, ow, ob);
    cudaEventRecord(evC, sC);

    // main: trig -> tableGEMM -> trans -> bev -> (join wpre) kp
    trig_kernel<<<(NTAB*EN + 255)/256, 256>>>();
    mma_gemm<6,16><<<gtab, 128, GSMEM>>>(w1, nullptr, nullptr, nullptr);          // table
    trans_kernel<<<(TOTC*QN + 255)/256, 256>>>(rp, ptm);
    bev_lookup<<<(TOTC*QN*(EN/4) + 255)/256, 256>>>(b1);
    cudaStreamWaitEvent(0, evC, 0);
    mma_gemm<1,32><<<gcav, 128, GSMEM>>>(nullptr, nullptr, x, out);               // kp (K=512)

    // join stream B, then the shortened attention chain
    cudaStreamWaitEvent(0, evB, 0);
    attn_kernel<<<NB*QN*NH*32/256, 256>>>(0);                                     // ctx1
    mma_gemm<7,16><<<gego, 128, GSMEM>>>(nullptr, in_b, x, out);                  // qpB
    attn_kernel<<<NB*QN*NH*32/256, 256>>>(1);                                     // cmix
    cudaStreamWaitEvent(0, evX, 0);
    mma_gemm<8,16><<<gego, 128, GSMEM>>>(ow, ob, x, out);                         // final -> out
}

// round 12
// speedup vs baseline: 1.5137x; 1.2372x over previous
#include <cuda_runtime.h>
#include <cuda_fp16.h>
#include <cstdint>

#define QN    2048
#define EN    256
#define TOTC  40
#define NB    8
#define LMAXC 5
#define NH    8
#define NTAB  2048

// ---------------- scratch ----------------
__device__ float g_trans [TOTC*QN*3];
__device__ float g_hidden[TOTC*QN*EN];
__device__ float g_kp    [TOTC*QN*EN];
__device__ float g_vp    [TOTC*QN*EN];
__device__ float g_qpA   [NB*QN*EN];
__device__ float g_qpB   [NB*QN*EN];
__device__ float g_ctx   [NB*QN*EN];
__device__ float g_table [3*NTAB*EN];
__device__ float g_trig  [NTAB*EN];
__device__ float g_wcat  [EN*512];
__device__ float g_bkp   [EN];
__device__ float g_wowq  [EN*EN];
__device__ float g_bqo   [EN];
__device__ float g_freq  [EN];
__device__ int   g_cav_batch[TOTC];
__device__ int   g_cav_local[TOTC];
__device__ int   g_batch_n  [NB];
__device__ int   g_batch_off[NB];

// ---------------- setup ----------------
__global__ void setup_kernel(const long long* __restrict__ rl64) {
    int t = threadIdx.x;
    if (t == 0) {
        bool ok64 = true;
        for (int b = 0; b < NB; b++) {
            long long v = rl64[b];
            if (v < 1 || v > LMAXC) ok64 = false;
        }
        const int* rl32 = (const int*)rl64;
        int acc = 0;
        for (int c = 0; c < TOTC; c++) { g_cav_batch[c] = 0; g_cav_local[c] = 0; }
        for (int b = 0; b < NB; b++) {
            int n = ok64 ? (int)rl64[b] : rl32[b];
            if (n < 1) n = 1;
            if (n > LMAXC) n = LMAXC;
            g_batch_n[b] = n; g_batch_off[b] = acc;
            for (int l = 0; l < n; l++) {
                int c = acc + l;
                if (c < TOTC) { g_cav_batch[c] = b; g_cav_local[c] = l; }
            }
            acc += n;
        }
    }
    for (int j = t; j < EN; j += blockDim.x) {
        float ex = (2.0f * (float)(j >> 1)) / (float)EN;
        g_freq[j] = 6.283185307179586f * expf(-ex * 9.210340371976184f);
    }
}

// ---------------- trig table (d-independent) ----------------
__global__ void trig_kernel() {
    int idx = blockIdx.x * blockDim.x + threadIdx.x;
    if (idx >= NTAB * EN) return;
    int j = idx & (EN - 1);
    int i = idx >> 8;
    float t = (float)i * (1.0f / (float)(NTAB - 1));
    float a = t * g_freq[j];
    g_trig[idx] = (j & 1) ? __cosf(a) : __sinf(a);
}

// ---------------- trans ----------------
__global__ void trans_kernel(const float* __restrict__ rp, const float* __restrict__ ptm) {
    int idx = blockIdx.x * blockDim.x + threadIdx.x;
    if (idx >= TOTC * QN) return;
    int c = idx / QN;
    int b = g_cav_batch[c], l = g_cav_local[c];
    float r0 = rp[idx*3+0] * 281.6f - 140.8f;
    float r1 = rp[idx*3+1] *  80.0f -  40.0f;
    float r2 = rp[idx*3+2] *   4.0f -   3.0f;
    const float* T = ptm + (size_t)((b * LMAXC + l) * LMAXC) * 16;
    #pragma unroll
    for (int i = 0; i < 3; i++) {
        float z = fmaf(T[i*4+0], r0, fmaf(T[i*4+1], r1, fmaf(T[i*4+2], r2, T[i*4+3])));
        g_trans[idx*3+i] = 1.0f / (1.0f + expf(-z));
    }
}

// ---------------- fused weight precompute: wcat/bkp + wowq/bqo ----------------
__global__ void wpre_kernel(const float* __restrict__ in_w, const float* __restrict__ in_b,
                            const float* __restrict__ w2,   const float* __restrict__ b2,
                            const float* __restrict__ ow,   const float* __restrict__ ob) {
    __shared__ float sWk[EN];
    __shared__ float sWq[EN];
    __shared__ float red[EN];
    int n = blockIdx.x, j = threadIdx.x;
    sWk[j] = in_w[(size_t)(EN + n)*EN + j];
    sWq[j] = in_w[(size_t)n*EN + j];
    __syncthreads();
    {
        float a0=0.f,a1=0.f,a2=0.f,a3=0.f;
        #pragma unroll 4
        for (int m = 0; m < EN; m += 4) {
            a0 = fmaf(sWk[m+0], w2[(size_t)(m+0)*EN + j], a0);
            a1 = fmaf(sWk[m+1], w2[(size_t)(m+1)*EN + j], a1);
            a2 = fmaf(sWk[m+2], w2[(size_t)(m+2)*EN + j], a2);
            a3 = fmaf(sWk[m+3], w2[(size_t)(m+3)*EN + j], a3);
        }
        g_wcat[(size_t)n*512 + j]      = sWk[j];
        g_wcat[(size_t)n*512 + EN + j] = (a0+a1)+(a2+a3);
    }
    {
        float a0=0.f,a1=0.f,a2=0.f,a3=0.f;
        #pragma unroll 4
        for (int m = 0; m < EN; m += 4) {
            a0 = fmaf(sWq[m+0], ow[(size_t)(m+0)*EN + j], a0);
            a1 = fmaf(sWq[m+1], ow[(size_t)(m+1)*EN + j], a1);
            a2 = fmaf(sWq[m+2], ow[(size_t)(m+2)*EN + j], a2);
            a3 = fmaf(sWq[m+3], ow[(size_t)(m+3)*EN + j], a3);
        }
        g_wowq[(size_t)n*EN + j] = (a0+a1)+(a2+a3);
    }
    red[j] = sWk[j] * b2[j];
    __syncthreads();
    for (int s = 128; s > 0; s >>= 1) {
        if (j < s) red[j] += red[j + s];
        __syncthreads();
    }
    if (j == 0) g_bkp[n] = in_b[EN + n] + red[0];
    __syncthreads();
    red[j] = sWq[j] * ob[j];
    __syncthreads();
    for (int s = 128; s > 0; s >>= 1) {
        if (j < s) red[j] += red[j + s];
        __syncthreads();
    }
    if (j == 0) g_bqo[n] = red[0];
}

// ---------------- hidden = relu(b1 + sum_d lerp(table_d, t_d)) ----------------
__global__ void bev_lookup(const float* __restrict__ b1) {
    int idx = blockIdx.x * blockDim.x + threadIdx.x;
    if (idx >= TOTC*QN*(EN/4)) return;
    int n4  = idx & 63;
    int row = idx >> 6;
    int cav = row >> 11;
    if (g_cav_local[cav] == 0 || g_batch_n[g_cav_batch[cav]] <= 1) return;
    float4 acc = *(const float4*)(b1 + n4*4);
    #pragma unroll
    for (int d = 0; d < 3; d++) {
        float tv = g_trans[(size_t)row*3 + d];
        float u  = tv * (float)(NTAB - 1);
        int i0 = (int)u;
        if (i0 < 0) i0 = 0;
        if (i0 > NTAB-2) i0 = NTAB-2;
        float w = u - (float)i0;
        const float* r = g_table + ((size_t)(d*NTAB + i0))*EN + n4*4;
        float4 a = *(const float4*)r;
        float4 b = *(const float4*)(r + EN);
        acc.x = fmaf(w, b.x - a.x, acc.x + a.x);
        acc.y = fmaf(w, b.y - a.y, acc.y + a.y);
        acc.z = fmaf(w, b.z - a.z, acc.z + a.z);
        acc.w = fmaf(w, b.w - a.w, acc.w + a.w);
    }
    float4 o = make_float4(fmaxf(acc.x,0.f), fmaxf(acc.y,0.f), fmaxf(acc.z,0.f), fmaxf(acc.w,0.f));
    *(float4*)(g_hidden + (size_t)row*EN + n4*4) = o;
}

// ================= single-pass fp16 tensor-core GEMM (64x64 warp tiles) =================
__device__ __forceinline__ uint32_t s2u(const void* p) {
    uint32_t a;
    asm("{ .reg .u64 t; cvta.to.shared.u64 t, %1; cvt.u32.u64 %0, t; }" : "=r"(a) : "l"(p));
    return a;
}
__device__ __forceinline__ void ldm4(uint32_t* f, uint32_t addr) {
    asm volatile("ldmatrix.sync.aligned.m8n8.x4.shared.b16 {%0,%1,%2,%3}, [%4];"
        : "=r"(f[0]),"=r"(f[1]),"=r"(f[2]),"=r"(f[3]) : "r"(addr));
}
__device__ __forceinline__ void mmahf(float* c, const uint32_t* a, const uint32_t* b) {
    asm volatile("mma.sync.aligned.m16n8k16.row.col.f32.f16.f16.f32 "
        "{%0,%1,%2,%3}, {%4,%5,%6,%7}, {%8,%9}, {%0,%1,%2,%3};"
        : "+f"(c[0]),"+f"(c[1]),"+f"(c[2]),"+f"(c[3])
        : "r"(a[0]),"r"(a[1]),"r"(a[2]),"r"(a[3]), "r"(b[0]),"r"(b[1]));
}
__device__ __forceinline__ uint32_t pkhf(float a, float b) {
    __half2 t = __floats2half2_rn(a, b);
    return *(uint32_t*)&t;
}

#define TSTR 24
#define TSZ  (128*TSTR)                    // halves per operand tile
#define GSMEM (2*2*TSZ*2)                  // 2 stages x 2 operands x TSZ halves x 2B = 24576

// MODE 1: kp   = [x|hidden] @ wcat^T + bkp               (K=512, neighbor cavs)
// MODE 2: vp   = x @ Wv^T + bv                           (neighbor cavs)
// MODE 3: qpA  = x_ego @ Wq^T + bq                       (multi batches)
// MODE 6: table = trig @ W1_d^T                          (bn -> d/nloc)
// MODE 7: qpB  = nm*(ctx@wowq^T + bqo) + nm*(qpA-bq)+bq  (multi batches)
// MODE 8: out_ego = ctx@Wo^T + nm2*x_ego + (nm2+nm)*bo   (final, writes OUT)
template<int MODE, int KT>
__global__ __launch_bounds__(128, 2) void mma_gemm(const float* __restrict__ W,
                                                   const float* __restrict__ bias,
                                                   const float* __restrict__ X,
                                                   float* __restrict__ OUT) {
    extern __shared__ __align__(16) __half sm[];

    const int bm = blockIdx.x, bn = blockIdx.y;
    int cav = 0;
    float scale = 1.0f;
    int bofs = 0;
    if (MODE == 1 || MODE == 2) {
        cav = bm >> 4;
        if (g_cav_local[cav] == 0 || g_batch_n[g_cav_batch[cav]] <= 1) return;
    } else if (MODE == 3 || MODE == 7 || MODE == 8) {
        int batch = bm >> 4;
        int n = g_batch_n[batch];
        if (n <= 1) return;
        scale = (float)(n - 1);
        bofs = g_batch_off[batch];
    }
    const int t    = threadIdx.x;
    const int lane = t & 31, wid = t >> 5;          // 4 warps
    const int wm   = wid & 1, wn = wid >> 1;        // 2x2 of 64x64 tiles
    const int m0   = bm * 128, n0 = bn * 128;
    const int lrow4 = t >> 2;                       // 0..31
    const int lf4   = t & 3;

    const int aoff = (wm*64 + (lane & 7) + ((lane >> 3) & 1) * 8) * TSTR + (lane >> 4) * 8;
    const int woff = (wn*64 + (lane & 7) + (lane >> 4) * 8) * TSTR + ((lane >> 3) & 1) * 8;

    const uint32_t smb = s2u(sm);

    float4 va[4], vw[4];
    auto ld = [&](int kt) {
        const int k0 = kt * 16 + lf4 * 4;
        #pragma unroll
        for (int rr = 0; rr < 4; rr++) {
            const int row = lrow4 + rr * 32;
            const int arow = m0 + row;
            const float* s;
            if (MODE == 1) {
                if (k0 < 256) { int q = arow & (QN-1); s = X + (size_t)q*(TOTC*EN) + cav*EN + k0; }
                else            s = g_hidden + (size_t)arow*EN + (k0 - 256);
            } else if (MODE == 2) {
                int q = arow & (QN-1); s = X + (size_t)q*(TOTC*EN) + cav*EN + k0;
            } else if (MODE == 3) {
                int q = arow & (QN-1); s = X + (size_t)q*(TOTC*EN) + bofs*EN + k0;
            } else if (MODE == 6) {
                s = g_trig + (size_t)arow*EN + k0;
            } else {
                s = g_ctx + (size_t)arow*EN + k0;
            }
            va[rr] = *(const float4*)s;
            const float* ws;
            if (MODE == 1)      ws = g_wcat + (size_t)(n0 + row)*512 + k0;
            else if (MODE == 6) {
                int d = bn >> 1, nloc = (bn & 1) * 128;
                ws = W + (size_t)(nloc + row)*768 + d*256 + k0;
            }
            else if (MODE == 7) ws = g_wowq + (size_t)(n0 + row)*EN + k0;
            else                ws = W + (size_t)(n0 + row)*EN + k0;
            vw[rr] = *(const float4*)ws;
        }
    };
    auto st = [&](int stage) {
        #pragma unroll
        for (int rr = 0; rr < 4; rr++) {
            const int eo = (lrow4 + rr*32) * TSTR + lf4 * 4;
            uint2 av = make_uint2(pkhf(va[rr].x, va[rr].y), pkhf(va[rr].z, va[rr].w));
            uint2 wv = make_uint2(pkhf(vw[rr].x, vw[rr].y), pkhf(vw[rr].z, vw[rr].w));
            *(uint2*)&sm[(stage*2+0)*TSZ + eo] = av;
            *(uint2*)&sm[(stage*2+1)*TSZ + eo] = wv;
        }
    };

    float acc[4][8][4] = {};

    ld(0); st(0);
    __syncthreads();
    for (int kt = 0; kt < KT; kt++) {
        if (kt + 1 < KT) ld(kt + 1);
        const int stage = kt & 1;
        const uint32_t bA = smb + (stage*2+0)*TSZ*2 + aoff*2;
        const uint32_t bW = smb + (stage*2+1)*TSZ*2 + woff*2;

        uint32_t A[4][4];
        #pragma unroll
        for (int ms = 0; ms < 4; ms++)
            ldm4(A[ms], bA + ms*16*TSTR*2);
        #pragma unroll
        for (int np = 0; np < 4; np++) {
            uint32_t B[4];
            ldm4(B, bW + np*16*TSTR*2);
            #pragma unroll
            for (int ms = 0; ms < 4; ms++) {
                mmahf(acc[ms][2*np],   A[ms], B);
                mmahf(acc[ms][2*np+1], A[ms], B+2);
            }
        }
        if (kt + 1 < KT) st(stage ^ 1);
        __syncthreads();
    }

    // epilogue
    #pragma unroll
    for (int ms = 0; ms < 4; ms++) {
        const int row = m0 + wm*64 + ms*16 + (lane >> 2);
        #pragma unroll
        for (int ns = 0; ns < 8; ns++) {
            const int nlocal = wn*64 + ns*8 + (lane & 3)*2;
            const int col = n0 + nlocal;
            #pragma unroll
            for (int h = 0; h < 2; h++) {
                const int r = row + h*8;
                float v0 = acc[ms][ns][2*h];
                float v1 = acc[ms][ns][2*h+1];
                if (MODE == 1) {
                    float* dst = g_kp + (size_t)r*EN + col;
                    *(float2*)dst = make_float2(v0 + g_bkp[col], v1 + g_bkp[col+1]);
                } else if (MODE == 2) {
                    float* dst = g_vp + (size_t)r*EN + col;
                    *(float2*)dst = make_float2(v0 + bias[col], v1 + bias[col+1]);
                } else if (MODE == 3) {
                    float* dst = g_qpA + (size_t)r*EN + col;
                    *(float2*)dst = make_float2(v0 + bias[col], v1 + bias[col+1]);
                } else if (MODE == 6) {
                    int d = bn >> 1, nloc = (bn & 1) * 128;
                    float* dst = g_table + ((size_t)(d*NTAB + r))*EN + nloc + nlocal;
                    *(float2*)dst = make_float2(v0, v1);
                } else if (MODE == 7) {
                    const size_t o = (size_t)r*EN + col;
                    float q10 = g_qpA[o], q11 = g_qpA[o+1];
                    float bq0 = bias[col], bq1 = bias[col+1];
                    float o0 = scale*(v0 + g_bqo[col])   + scale*(q10 - bq0) + bq0;
                    float o1 = scale*(v1 + g_bqo[col+1]) + scale*(q11 - bq1) + bq1;
                    *(float2*)(g_qpB + o) = make_float2(o0, o1);
                } else {
                    const float nm2 = scale * scale;
                    int q = r & (QN - 1);
                    const float* xr = X + (size_t)q*(TOTC*EN) + bofs*EN + col;
                    float o0 = v0 + nm2*xr[0] + (nm2 + scale)*bias[col];
                    float o1 = v1 + nm2*xr[1] + (nm2 + scale)*bias[col+1];
                    float* dst = OUT + ((size_t)q*TOTC + bofs)*EN + col;
                    *(float2*)dst = make_float2(o0, o1);
                }
            }
        }
    }
}

// ---------------- degenerate attention ----------------
__global__ void attn_kernel(int it) {
    int w = (blockIdx.x * blockDim.x + threadIdx.x) >> 5;
    int lane = threadIdx.x & 31;
    if (w >= NB * QN * NH) return;
    int h  = w & 7;
    int bq = w >> 3;
    int b  = bq >> 11;
    int q  = bq & (QN - 1);
    int n  = g_batch_n[b];
    if (n <= 1) return;
    int nm  = n - 1;
    int off = g_batch_off[b];
    int col = h * 32 + lane;

    const float* qp = (it == 0) ? g_qpA : g_qpB;
    float qv = qp[(size_t)bq*EN + col];
    float sc[LMAXC - 1];
    for (int m = 0; m < nm; m++) {
        int c = off + 1 + m;
        float p = qv * g_kp[(size_t)(c*QN + q)*EN + col];
        #pragma unroll
        for (int o = 16; o; o >>= 1) p += __shfl_xor_sync(0xffffffffu, p, o);
        sc[m] = p * 0.17677669529663687f;
    }
    float mx = -1e30f;
    for (int m = 0; m < nm; m++) mx = fmaxf(mx, sc[m]);
    float s = 0.0f, wt[LMAXC - 1];
    for (int m = 0; m < nm; m++) { wt[m] = __expf(sc[m] - mx); s += wt[m]; }
    float inv = 1.0f / s;
    float ctx = 0.0f;
    for (int m = 0; m < nm; m++) {
        int c = off + 1 + m;
        ctx = fmaf(wt[m] * inv, g_vp[(size_t)(c*QN + q)*EN + col], ctx);
    }
    const size_t o = (size_t)bq*EN + col;
    if (it == 0) {
        g_ctx[o] = ctx;
    } else {
        float fnm = (float)nm;
        g_ctx[o] = fnm*fnm*g_ctx[o] + fnm*ctx;
    }
}

// ---------------- launch (fork-join multi-stream) ----------------
extern "C" void kernel_launch(void* const* d_in, const int* in_sizes, int n_in,
                              void* d_out, int out_size) {
    const float*     x    = (const float*)d_in[0];
    const float*     rp   = (const float*)d_in[1];
    const float*     ptm  = (const float*)d_in[2];
    const long long* rl   = (const long long*)d_in[3];
    const float*     in_w = (const float*)d_in[4];
    const float*     in_b = (const float*)d_in[5];
    const float*     ow   = (const float*)d_in[6];
    const float*     ob   = (const float*)d_in[7];
    const float*     w1   = (const float*)d_in[8];
    const float*     b1   = (const float*)d_in[9];
    const float*     w2   = (const float*)d_in[10];
    const float*     b2   = (const float*)d_in[11];
    float* out = (float*)d_out;

    static cudaStream_t sB = nullptr, sC = nullptr, sD = nullptr;
    static cudaEvent_t  ev0 = nullptr, evB = nullptr, evC = nullptr, evX = nullptr;
    if (sB == nullptr) {
        cudaStreamCreateWithFlags(&sB, cudaStreamNonBlocking);
        cudaStreamCreateWithFlags(&sC, cudaStreamNonBlocking);
        cudaStreamCreateWithFlags(&sD, cudaStreamNonBlocking);
        cudaEventCreateWithFlags(&ev0, cudaEventDisableTiming);
        cudaEventCreateWithFlags(&evB, cudaEventDisableTiming);
        cudaEventCreateWithFlags(&evC, cudaEventDisableTiming);
        cudaEventCreateWithFlags(&evX, cudaEventDisableTiming);
    }

    dim3 gcav(TOTC*QN/128, 2);      // 640 x 2
    dim3 gego(NB*QN/128, 2);        // 128 x 2
    dim3 gtab(NTAB/128, 6);         // 16 x 6

    // main: setup then fork everything off ev0
    setup_kernel<<<1, 256>>>(rl);
    cudaEventRecord(ev0, 0);

    // stream D: bulk copy x -> out
    cudaStreamWaitEvent(sD, ev0, 0);
    cudaMemcpyAsync(out, x, (size_t)QN*TOTC*EN*sizeof(float),
                    cudaMemcpyDeviceToDevice, sD);
    cudaEventRecord(evX, sD);

    // stream B: vp + qpA
    cudaStreamWaitEvent(sB, ev0, 0);
    mma_gemm<2,16><<<gcav, 128, GSMEM, sB>>>(in_w + 512*EN, in_b + 512, x, out);  // vp
    mma_gemm<3,16><<<gego, 128, GSMEM, sB>>>(in_w, in_b, x, out);                 // qpA
    cudaEventRecord(evB, sB);

    // stream C: fused weight precompute
    cudaStreamWaitEvent(sC, ev0, 0);
    wpre_kernel<<<EN, EN, 0, sC>>>(in_w, in_b, w2, b2, ow, ob);
    cudaEventRecord(evC, sC);

    // main: trig -> tableGEMM -> trans -> bev -> (join wpre) kp
    trig_kernel<<<(NTAB*EN + 255)/256, 256>>>();
    mma_gemm<6,16><<<gtab, 128, GSMEM>>>(w1, nullptr, nullptr, nullptr);          // table
    trans_kernel<<<(TOTC*QN + 255)/256, 256>>>(rp, ptm);
    bev_lookup<<<(TOTC*QN*(EN/4) + 255)/256, 256>>>(b1);
    cudaStreamWaitEvent(0, evC, 0);
    mma_gemm<1,32><<<gcav, 128, GSMEM>>>(nullptr, nullptr, x, out);               // kp (K=512)

    // join stream B, then the shortened attention chain
    cudaStreamWaitEvent(0, evB, 0);
    attn_kernel<<<NB*QN*NH*32/256, 256>>>(0);                                     // ctx1
    mma_gemm<7,16><<<gego, 128, GSMEM>>>(nullptr, in_b, x, out);                  // qpB
    attn_kernel<<<NB*QN*NH*32/256, 256>>>(1);                                     // cmix
    cudaStreamWaitEvent(0, evX, 0);
    mma_gemm<8,16><<<gego, 128, GSMEM>>>(ow, ob, x, out);                         // final -> out
}

// round 13
// speedup vs baseline: 1.5985x; 1.0560x over previous
#include <cuda_runtime.h>
#include <cuda_fp16.h>
#include <cstdint>

#define QN    2048
#define EN    256
#define TOTC  40
#define NB    8
#define LMAXC 5
#define NH    8
#define NTAB  2048

// ---------------- scratch ----------------
__device__ float  g_trans [TOTC*QN*3];
__device__ __half g_hidden[TOTC*QN*EN];
__device__ __half g_kp    [TOTC*QN*EN];
__device__ __half g_vp    [TOTC*QN*EN];
__device__ __half g_qpA   [NB*QN*EN];
__device__ __half g_qpB   [NB*QN*EN];
__device__ __half g_ctx   [NB*QN*EN];
__device__ float  g_table [3*NTAB*EN];
__device__ float  g_trig  [NTAB*EN];
__device__ float  g_wcat  [EN*512];
__device__ float  g_bkp   [EN];
__device__ float  g_wowq  [EN*EN];
__device__ float  g_bqo   [EN];
__device__ float  g_freq  [EN];
__device__ int    g_cav_batch[TOTC];
__device__ int    g_cav_local[TOTC];
__device__ int    g_batch_n  [NB];
__device__ int    g_batch_off[NB];

// ---------------- setup ----------------
__global__ void setup_kernel(const long long* __restrict__ rl64) {
    int t = threadIdx.x;
    if (t == 0) {
        bool ok64 = true;
        for (int b = 0; b < NB; b++) {
            long long v = rl64[b];
            if (v < 1 || v > LMAXC) ok64 = false;
        }
        const int* rl32 = (const int*)rl64;
        int acc = 0;
        for (int c = 0; c < TOTC; c++) { g_cav_batch[c] = 0; g_cav_local[c] = 0; }
        for (int b = 0; b < NB; b++) {
            int n = ok64 ? (int)rl64[b] : rl32[b];
            if (n < 1) n = 1;
            if (n > LMAXC) n = LMAXC;
            g_batch_n[b] = n; g_batch_off[b] = acc;
            for (int l = 0; l < n; l++) {
                int c = acc + l;
                if (c < TOTC) { g_cav_batch[c] = b; g_cav_local[c] = l; }
            }
            acc += n;
        }
    }
    for (int j = t; j < EN; j += blockDim.x) {
        float ex = (2.0f * (float)(j >> 1)) / (float)EN;
        g_freq[j] = 6.283185307179586f * expf(-ex * 9.210340371976184f);
    }
}

// ---------------- trig table ----------------
__global__ void trig_kernel() {
    int idx = blockIdx.x * blockDim.x + threadIdx.x;
    if (idx >= NTAB * EN) return;
    int j = idx & (EN - 1);
    int i = idx >> 8;
    float t = (float)i * (1.0f / (float)(NTAB - 1));
    float a = t * g_freq[j];
    g_trig[idx] = (j & 1) ? __cosf(a) : __sinf(a);
}

// ---------------- trans ----------------
__global__ void trans_kernel(const float* __restrict__ rp, const float* __restrict__ ptm) {
    int idx = blockIdx.x * blockDim.x + threadIdx.x;
    if (idx >= TOTC * QN) return;
    int c = idx / QN;
    int b = g_cav_batch[c], l = g_cav_local[c];
    float r0 = rp[idx*3+0] * 281.6f - 140.8f;
    float r1 = rp[idx*3+1] *  80.0f -  40.0f;
    float r2 = rp[idx*3+2] *   4.0f -   3.0f;
    const float* T = ptm + (size_t)((b * LMAXC + l) * LMAXC) * 16;
    #pragma unroll
    for (int i = 0; i < 3; i++) {
        float z = fmaf(T[i*4+0], r0, fmaf(T[i*4+1], r1, fmaf(T[i*4+2], r2, T[i*4+3])));
        g_trans[idx*3+i] = 1.0f / (1.0f + expf(-z));
    }
}

// ---------------- fused weight precompute ----------------
__global__ void wpre_kernel(const float* __restrict__ in_w, const float* __restrict__ in_b,
                            const float* __restrict__ w2,   const float* __restrict__ b2,
                            const float* __restrict__ ow,   const float* __restrict__ ob) {
    __shared__ float sWk[EN];
    __shared__ float sWq[EN];
    __shared__ float red[EN];
    int n = blockIdx.x, j = threadIdx.x;
    sWk[j] = in_w[(size_t)(EN + n)*EN + j];
    sWq[j] = in_w[(size_t)n*EN + j];
    __syncthreads();
    {
        float a0=0.f,a1=0.f,a2=0.f,a3=0.f;
        #pragma unroll 4
        for (int m = 0; m < EN; m += 4) {
            a0 = fmaf(sWk[m+0], w2[(size_t)(m+0)*EN + j], a0);
            a1 = fmaf(sWk[m+1], w2[(size_t)(m+1)*EN + j], a1);
            a2 = fmaf(sWk[m+2], w2[(size_t)(m+2)*EN + j], a2);
            a3 = fmaf(sWk[m+3], w2[(size_t)(m+3)*EN + j], a3);
        }
        g_wcat[(size_t)n*512 + j]      = sWk[j];
        g_wcat[(size_t)n*512 + EN + j] = (a0+a1)+(a2+a3);
    }
    {
        float a0=0.f,a1=0.f,a2=0.f,a3=0.f;
        #pragma unroll 4
        for (int m = 0; m < EN; m += 4) {
            a0 = fmaf(sWq[m+0], ow[(size_t)(m+0)*EN + j], a0);
            a1 = fmaf(sWq[m+1], ow[(size_t)(m+1)*EN + j], a1);
            a2 = fmaf(sWq[m+2], ow[(size_t)(m+2)*EN + j], a2);
            a3 = fmaf(sWq[m+3], ow[(size_t)(m+3)*EN + j], a3);
        }
        g_wowq[(size_t)n*EN + j] = (a0+a1)+(a2+a3);
    }
    red[j] = sWk[j] * b2[j];
    __syncthreads();
    for (int s = 128; s > 0; s >>= 1) {
        if (j < s) red[j] += red[j + s];
        __syncthreads();
    }
    if (j == 0) g_bkp[n] = in_b[EN + n] + red[0];
    __syncthreads();
    red[j] = sWq[j] * ob[j];
    __syncthreads();
    for (int s = 128; s > 0; s >>= 1) {
        if (j < s) red[j] += red[j + s];
        __syncthreads();
    }
    if (j == 0) g_bqo[n] = red[0];
}

// ---------------- hidden = relu(b1 + sum_d lerp(table_d, t_d)) -> fp16 ----------------
__global__ void bev_lookup(const float* __restrict__ b1) {
    int idx = blockIdx.x * blockDim.x + threadIdx.x;
    if (idx >= TOTC*QN*(EN/4)) return;
    int n4  = idx & 63;
    int row = idx >> 6;
    int cav = row >> 11;
    if (g_cav_local[cav] == 0 || g_batch_n[g_cav_batch[cav]] <= 1) return;
    float4 acc = *(const float4*)(b1 + n4*4);
    #pragma unroll
    for (int d = 0; d < 3; d++) {
        float tv = g_trans[(size_t)row*3 + d];
        float u  = tv * (float)(NTAB - 1);
        int i0 = (int)u;
        if (i0 < 0) i0 = 0;
        if (i0 > NTAB-2) i0 = NTAB-2;
        float w = u - (float)i0;
        const float* r = g_table + ((size_t)(d*NTAB + i0))*EN + n4*4;
        float4 a = *(const float4*)r;
        float4 b = *(const float4*)(r + EN);
        acc.x = fmaf(w, b.x - a.x, acc.x + a.x);
        acc.y = fmaf(w, b.y - a.y, acc.y + a.y);
        acc.z = fmaf(w, b.z - a.z, acc.z + a.z);
        acc.w = fmaf(w, b.w - a.w, acc.w + a.w);
    }
    __half2 h0 = __floats2half2_rn(fmaxf(acc.x,0.f), fmaxf(acc.y,0.f));
    __half2 h1 = __floats2half2_rn(fmaxf(acc.z,0.f), fmaxf(acc.w,0.f));
    uint2 pk = make_uint2(*(uint32_t*)&h0, *(uint32_t*)&h1);
    *(uint2*)&g_hidden[(size_t)row*EN + n4*4] = pk;
}

// ================= single-pass fp16 tensor-core GEMM (64x64 warp tiles) =================
__device__ __forceinline__ uint32_t s2u(const void* p) {
    uint32_t a;
    asm("{ .reg .u64 t; cvta.to.shared.u64 t, %1; cvt.u32.u64 %0, t; }" : "=r"(a) : "l"(p));
    return a;
}
__device__ __forceinline__ void ldm4(uint32_t* f, uint32_t addr) {
    asm volatile("ldmatrix.sync.aligned.m8n8.x4.shared.b16 {%0,%1,%2,%3}, [%4];"
        : "=r"(f[0]),"=r"(f[1]),"=r"(f[2]),"=r"(f[3]) : "r"(addr));
}
__device__ __forceinline__ void mmahf(float* c, const uint32_t* a, const uint32_t* b) {
    asm volatile("mma.sync.aligned.m16n8k16.row.col.f32.f16.f16.f32 "
        "{%0,%1,%2,%3}, {%4,%5,%6,%7}, {%8,%9}, {%0,%1,%2,%3};"
        : "+f"(c[0]),"+f"(c[1]),"+f"(c[2]),"+f"(c[3])
        : "r"(a[0]),"r"(a[1]),"r"(a[2]),"r"(a[3]), "r"(b[0]),"r"(b[1]));
}
__device__ __forceinline__ uint32_t pkhf(float a, float b) {
    __half2 t = __floats2half2_rn(a, b);
    return *(uint32_t*)&t;
}

#define TSTR 24
#define TSZ  (128*TSTR)
#define GSMEM (2*2*TSZ*2)     // 24576 B

// MODE 1: kp   = [x|hidden] @ wcat^T + bkp               (K=512, neighbor cavs)
// MODE 2: vp   = x @ Wv^T + bv                           (neighbor cavs)
// MODE 3: qpA  = x_ego @ Wq^T + bq                       (multi batches)
// MODE 6: table = trig @ W1_d^T                          (bn -> d/nloc)
// MODE 7: qpB  = nm*(ctx@wowq^T + bqo) + nm*(qpA-bq)+bq  (multi batches)
// MODE 8: out_ego = ctx@Wo^T + nm2*x_ego + (nm2+nm)*bo   (final, writes OUT)
template<int MODE, int KT>
__global__ __launch_bounds__(128, 2) void mma_gemm(const float* __restrict__ W,
                                                   const float* __restrict__ bias,
                                                   const float* __restrict__ X,
                                                   float* __restrict__ OUT) {
    extern __shared__ __align__(16) __half sm[];

    const int bm = blockIdx.x, bn = blockIdx.y;
    int cav = 0;
    float scale = 1.0f;
    int bofs = 0;
    if (MODE == 1 || MODE == 2) {
        cav = bm >> 4;
        if (g_cav_local[cav] == 0 || g_batch_n[g_cav_batch[cav]] <= 1) return;
    } else if (MODE == 3 || MODE == 7 || MODE == 8) {
        int batch = bm >> 4;
        int n = g_batch_n[batch];
        if (n <= 1) return;
        scale = (float)(n - 1);
        bofs = g_batch_off[batch];
    }
    const int t    = threadIdx.x;
    const int lane = t & 31, wid = t >> 5;
    const int wm   = wid & 1, wn = wid >> 1;
    const int m0   = bm * 128, n0 = bn * 128;
    const int lrow4 = t >> 2;
    const int lf4   = t & 3;

    const int aoff = (wm*64 + (lane & 7) + ((lane >> 3) & 1) * 8) * TSTR + (lane >> 4) * 8;
    const int woff = (wn*64 + (lane & 7) + (lane >> 4) * 8) * TSTR + ((lane >> 3) & 1) * 8;

    const uint32_t smb = s2u(sm);

    uint2  araw[4];            // packed 4 halves (A operand)
    float4 vw[4];
    auto ld = [&](int kt) {
        const int k0 = kt * 16 + lf4 * 4;
        #pragma unroll
        for (int rr = 0; rr < 4; rr++) {
            const int row = lrow4 + rr * 32;
            const int arow = m0 + row;
            if (MODE == 1) {
                if (k0 < 256) {
                    int q = arow & (QN-1);
                    const float* s = X + (size_t)q*(TOTC*EN) + cav*EN + k0;
                    float4 v = *(const float4*)s;
                    araw[rr] = make_uint2(pkhf(v.x, v.y), pkhf(v.z, v.w));
                } else {
                    araw[rr] = *(const uint2*)&g_hidden[(size_t)arow*EN + (k0 - 256)];
                }
            } else if (MODE == 2) {
                int q = arow & (QN-1);
                const float* s = X + (size_t)q*(TOTC*EN) + cav*EN + k0;
                float4 v = *(const float4*)s;
                araw[rr] = make_uint2(pkhf(v.x, v.y), pkhf(v.z, v.w));
            } else if (MODE == 3) {
                int q = arow & (QN-1);
                const float* s = X + (size_t)q*(TOTC*EN) + bofs*EN + k0;
                float4 v = *(const float4*)s;
                araw[rr] = make_uint2(pkhf(v.x, v.y), pkhf(v.z, v.w));
            } else if (MODE == 6) {
                const float* s = g_trig + (size_t)arow*EN + k0;
                float4 v = *(const float4*)s;
                araw[rr] = make_uint2(pkhf(v.x, v.y), pkhf(v.z, v.w));
            } else {
                araw[rr] = *(const uint2*)&g_ctx[(size_t)arow*EN + k0];
            }
            const float* ws;
            if (MODE == 1)      ws = g_wcat + (size_t)(n0 + row)*512 + k0;
            else if (MODE == 6) {
                int d = bn >> 1, nloc = (bn & 1) * 128;
                ws = W + (size_t)(nloc + row)*768 + d*256 + k0;
            }
            else if (MODE == 7) ws = g_wowq + (size_t)(n0 + row)*EN + k0;
            else                ws = W + (size_t)(n0 + row)*EN + k0;
            vw[rr] = *(const float4*)ws;
        }
    };
    auto st = [&](int stage) {
        #pragma unroll
        for (int rr = 0; rr < 4; rr++) {
            const int eo = (lrow4 + rr*32) * TSTR + lf4 * 4;
            *(uint2*)&sm[(stage*2+0)*TSZ + eo] = araw[rr];
            uint2 wv = make_uint2(pkhf(vw[rr].x, vw[rr].y), pkhf(vw[rr].z, vw[rr].w));
            *(uint2*)&sm[(stage*2+1)*TSZ + eo] = wv;
        }
    };

    float acc[4][8][4] = {};

    ld(0); st(0);
    __syncthreads();
    for (int kt = 0; kt < KT; kt++) {
        if (kt + 1 < KT) ld(kt + 1);
        const int stage = kt & 1;
        const uint32_t bA = smb + (stage*2+0)*TSZ*2 + aoff*2;
        const uint32_t bW = smb + (stage*2+1)*TSZ*2 + woff*2;

        uint32_t A[4][4];
        #pragma unroll
        for (int ms = 0; ms < 4; ms++)
            ldm4(A[ms], bA + ms*16*TSTR*2);
        #pragma unroll
        for (int np = 0; np < 4; np++) {
            uint32_t B[4];
            ldm4(B, bW + np*16*TSTR*2);
            #pragma unroll
            for (int ms = 0; ms < 4; ms++) {
                mmahf(acc[ms][2*np],   A[ms], B);
                mmahf(acc[ms][2*np+1], A[ms], B+2);
            }
        }
        if (kt + 1 < KT) st(stage ^ 1);
        __syncthreads();
    }

    // epilogue
    #pragma unroll
    for (int ms = 0; ms < 4; ms++) {
        const int row = m0 + wm*64 + ms*16 + (lane >> 2);
        #pragma unroll
        for (int ns = 0; ns < 8; ns++) {
            const int nlocal = wn*64 + ns*8 + (lane & 3)*2;
            const int col = n0 + nlocal;
            #pragma unroll
            for (int h = 0; h < 2; h++) {
                const int r = row + h*8;
                float v0 = acc[ms][ns][2*h];
                float v1 = acc[ms][ns][2*h+1];
                if (MODE == 1) {
                    uint32_t pk = pkhf(v0 + g_bkp[col], v1 + g_bkp[col+1]);
                    *(uint32_t*)&g_kp[(size_t)r*EN + col] = pk;
                } else if (MODE == 2) {
                    uint32_t pk = pkhf(v0 + bias[col], v1 + bias[col+1]);
                    *(uint32_t*)&g_vp[(size_t)r*EN + col] = pk;
                } else if (MODE == 3) {
                    uint32_t pk = pkhf(v0 + bias[col], v1 + bias[col+1]);
                    *(uint32_t*)&g_qpA[(size_t)r*EN + col] = pk;
                } else if (MODE == 6) {
                    int d = bn >> 1, nloc = (bn & 1) * 128;
                    float* dst = g_table + ((size_t)(d*NTAB + r))*EN + nloc + nlocal;
                    *(float2*)dst = make_float2(v0, v1);
                } else if (MODE == 7) {
                    const size_t o = (size_t)r*EN + col;
                    float q10 = __half2float(g_qpA[o]);
                    float q11 = __half2float(g_qpA[o+1]);
                    float bq0 = bias[col], bq1 = bias[col+1];
                    float o0 = scale*(v0 + g_bqo[col])   + scale*(q10 - bq0) + bq0;
                    float o1 = scale*(v1 + g_bqo[col+1]) + scale*(q11 - bq1) + bq1;
                    *(uint32_t*)&g_qpB[o] = pkhf(o0, o1);
                } else {
                    const float nm2 = scale * scale;
                    int q = r & (QN - 1);
                    const float* xr = X + (size_t)q*(TOTC*EN) + bofs*EN + col;
                    float o0 = v0 + nm2*xr[0] + (nm2 + scale)*bias[col];
                    float o1 = v1 + nm2*xr[1] + (nm2 + scale)*bias[col+1];
                    float* dst = OUT + ((size_t)q*TOTC + bofs)*EN + col;
                    *(float2*)dst = make_float2(o0, o1);
                }
            }
        }
    }
}

// ---------------- degenerate attention (fp16 inputs, fp32 math) ----------------
__global__ void attn_kernel(int it) {
    int w = (blockIdx.x * blockDim.x + threadIdx.x) >> 5;
    int lane = threadIdx.x & 31;
    if (w >= NB * QN * NH) return;
    int h  = w & 7;
    int bq = w >> 3;
    int b  = bq >> 11;
    int q  = bq & (QN - 1);
    int n  = g_batch_n[b];
    if (n <= 1) return;
    int nm  = n - 1;
    int off = g_batch_off[b];
    int col = h * 32 + lane;

    const __half* qp = (it == 0) ? g_qpA : g_qpB;
    float qv = __half2float(qp[(size_t)bq*EN + col]);
    float sc[LMAXC - 1];
    for (int m = 0; m < nm; m++) {
        int c = off + 1 + m;
        float p = qv * __half2float(g_kp[(size_t)(c*QN + q)*EN + col]);
        #pragma unroll
        for (int o = 16; o; o >>= 1) p += __shfl_xor_sync(0xffffffffu, p, o);
        sc[m] = p * 0.17677669529663687f;
    }
    float mx = -1e30f;
    for (int m = 0; m < nm; m++) mx = fmaxf(mx, sc[m]);
    float s = 0.0f, wt[LMAXC - 1];
    for (int m = 0; m < nm; m++) { wt[m] = __expf(sc[m] - mx); s += wt[m]; }
    float inv = 1.0f / s;
    float ctx = 0.0f;
    for (int m = 0; m < nm; m++) {
        int c = off + 1 + m;
        ctx = fmaf(wt[m] * inv, __half2float(g_vp[(size_t)(c*QN + q)*EN + col]), ctx);
    }
    const size_t o = (size_t)bq*EN + col;
    if (it == 0) {
        g_ctx[o] = __float2half(ctx);
    } else {
        float fnm = (float)nm;
        float old = __half2float(g_ctx[o]);
        g_ctx[o] = __float2half(fnm*fnm*old + fnm*ctx);
    }
}

// ---------------- launch (fork-join multi-stream) ----------------
extern "C" void kernel_launch(void* const* d_in, const int* in_sizes, int n_in,
                              void* d_out, int out_size) {
    const float*     x    = (const float*)d_in[0];
    const float*     rp   = (const float*)d_in[1];
    const float*     ptm  = (const float*)d_in[2];
    const long long* rl   = (const long long*)d_in[3];
    const float*     in_w = (const float*)d_in[4];
    const float*     in_b = (const float*)d_in[5];
    const float*     ow   = (const float*)d_in[6];
    const float*     ob   = (const float*)d_in[7];
    const float*     w1   = (const float*)d_in[8];
    const float*     b1   = (const float*)d_in[9];
    const float*     w2   = (const float*)d_in[10];
    const float*     b2   = (const float*)d_in[11];
    float* out = (float*)d_out;

    static cudaStream_t sB = nullptr, sC = nullptr, sD = nullptr;
    static cudaEvent_t  ev0 = nullptr, evB = nullptr, evC = nullptr, evX = nullptr;
    if (sB == nullptr) {
        cudaStreamCreateWithFlags(&sB, cudaStreamNonBlocking);
        cudaStreamCreateWithFlags(&sC, cudaStreamNonBlocking);
        cudaStreamCreateWithFlags(&sD, cudaStreamNonBlocking);
        cudaEventCreateWithFlags(&ev0, cudaEventDisableTiming);
        cudaEventCreateWithFlags(&evB, cudaEventDisableTiming);
        cudaEventCreateWithFlags(&evC, cudaEventDisableTiming);
        cudaEventCreateWithFlags(&evX, cudaEventDisableTiming);
    }

    dim3 gcav(TOTC*QN/128, 2);      // 640 x 2
    dim3 gego(NB*QN/128, 2);        // 128 x 2
    dim3 gtab(NTAB/128, 6);         // 16 x 6

    // main: setup then fork everything off ev0
    setup_kernel<<<1, 256>>>(rl);
    cudaEventRecord(ev0, 0);

    // stream D: bulk copy x -> out
    cudaStreamWaitEvent(sD, ev0, 0);
    cudaMemcpyAsync(out, x, (size_t)QN*TOTC*EN*sizeof(float),
                    cudaMemcpyDeviceToDevice, sD);
    cudaEventRecord(evX, sD);

    // stream B: vp + qpA
    cudaStreamWaitEvent(sB, ev0, 0);
    mma_gemm<2,16><<<gcav, 128, GSMEM, sB>>>(in_w + 512*EN, in_b + 512, x, out);  // vp
    mma_gemm<3,16><<<gego, 128, GSMEM, sB>>>(in_w, in_b, x, out);                 // qpA
    cudaEventRecord(evB, sB);

    // stream C: fused weight precompute
    cudaStreamWaitEvent(sC, ev0, 0);
    wpre_kernel<<<EN, EN, 0, sC>>>(in_w, in_b, w2, b2, ow, ob);
    cudaEventRecord(evC, sC);

    // main: trig -> tableGEMM -> trans -> bev -> (join wpre) kp
    trig_kernel<<<(NTAB*EN + 255)/256, 256>>>();
    mma_gemm<6,16><<<gtab, 128, GSMEM>>>(w1, nullptr, nullptr, nullptr);          // table
    trans_kernel<<<(TOTC*QN + 255)/256, 256>>>(rp, ptm);
    bev_lookup<<<(TOTC*QN*(EN/4) + 255)/256, 256>>>(b1);
    cudaStreamWaitEvent(0, evC, 0);
    mma_gemm<1,32><<<gcav, 128, GSMEM>>>(nullptr, nullptr, x, out);               // kp (K=512)

    // join stream B, then the shortened attention chain
    cudaStreamWaitEvent(0, evB, 0);
    attn_kernel<<<NB*QN*NH*32/256, 256>>>(0);                                     // ctx1
    mma_gemm<7,16><<<gego, 128, GSMEM>>>(nullptr, in_b, x, out);                  // qpB
    attn_kernel<<<NB*QN*NH*32/256, 256>>>(1);                                     // cmix
    cudaStreamWaitEvent(0, evX, 0);
    mma_gemm<8,16><<<gego, 128, GSMEM>>>(ow, ob, x, out);                         // final -> out
}